// round 10
// baseline (speedup 1.0000x reference)
#include <cuda_runtime.h>
#include <cuda_fp16.h>
#include <cstdint>
#include <cstddef>

#define MM    3
#define NN    100000
#define DIN   128
#define DH    64
#define EDGES 1600000
#define NSEG  (MM * NN)
#define CAP   64                         // per-segment slot capacity (P(deg>64)~1e-20)

// ---------------- scratch (device globals; no allocations) ----------------
__device__ __half g_proj[(size_t)MM * NN * DH];  // 38.4 MB [m][n][h] fp16
__device__ __half g_hn  [(size_t)NN * MM * DH];  // 38.4 MB [n][m][h] fp16
__device__ int    g_count[NSEG];                 // per-(m,dst) degree
__device__ int    g_eidx[(size_t)NSEG * CAP];    // 76.8 MB binned src ids
__device__ float  g_logits[MM];

// packed f32x2 FMA (FFMA2)
__device__ __forceinline__ float2 ffma2(float2 a, float2 b, float2 c) {
    unsigned long long au = *reinterpret_cast<unsigned long long*>(&a);
    unsigned long long bu = *reinterpret_cast<unsigned long long*>(&b);
    unsigned long long cu = *reinterpret_cast<unsigned long long*>(&c);
    unsigned long long du;
    asm("fma.rn.f32x2 %0, %1, %2, %3;" : "=l"(du) : "l"(au), "l"(bu), "l"(cu));
    return *reinterpret_cast<float2*>(&du);
}

__device__ __forceinline__ float tanh_hw(float x) {
    float y;
    asm("tanh.approx.f32 %0, %1;" : "=f"(y) : "f"(x));
    return y;
}

// ---------------- K1: proj[m] = feats[m] @ W[m]  (per-m launch) ------------
// 128 threads, 128 rows x 64 cols per block. Thread tile 4 rows (stride 32)
// x 16 cols -> 64 acc regs. __launch_bounds__(128,4): 4 blocks/SM, 16 warps.
#define FPAD 36
__global__ __launch_bounds__(128, 4) void k_proj(const float* __restrict__ feats,
                                                 const float* __restrict__ W, int m) {
    __shared__ float sF[128 * FPAD];   // 18.4 KB
    __shared__ float sW[32 * 64];      // 8 KB

    const int node0 = blockIdx.x * 128;
    const int t  = threadIdx.x;
    const int rg = t >> 2;             // 0..31
    const int cg = t & 3;

    const float* fbase = feats + (size_t)m * NN * DIN;
    const float* wbase = W     + (size_t)m * DIN * DH;

    float2 acc[4][8];
    #pragma unroll
    for (int i = 0; i < 4; i++)
        #pragma unroll
        for (int j = 0; j < 8; j++) acc[i][j] = make_float2(0.f, 0.f);

    for (int kt = 0; kt < DIN; kt += 32) {
        __syncthreads();
        // feats tile: 128 rows x 32 k = 1024 float4 / 128 thr = 8 each
        #pragma unroll
        for (int it = 0; it < 8; it++) {
            int idx = t + 128 * it;
            int row = idx >> 3;
            int k4  = idx & 7;
            int gn  = node0 + row;
            float4 v = make_float4(0.f, 0.f, 0.f, 0.f);
            if (gn < NN)
                v = *(const float4*)(fbase + (size_t)gn * DIN + kt + k4 * 4);
            *(float4*)&sF[row * FPAD + k4 * 4] = v;
        }
        // W slice: 32 rows x 64 cols = 512 float4 / 128 thr = 4 each
        #pragma unroll
        for (int it = 0; it < 4; it++) {
            int idx = t + 128 * it;
            ((float4*)sW)[idx] = ((const float4*)(wbase + (size_t)kt * DH))[idx];
        }
        __syncthreads();

        #pragma unroll
        for (int k = 0; k < 32; k++) {
            float f[4];
            #pragma unroll
            for (int i = 0; i < 4; i++) f[i] = sF[(rg + 32 * i) * FPAD + k];
            float4 w0 = *(const float4*)&sW[k * 64 + cg * 16 + 0];
            float4 w1 = *(const float4*)&sW[k * 64 + cg * 16 + 4];
            float4 w2 = *(const float4*)&sW[k * 64 + cg * 16 + 8];
            float4 w3 = *(const float4*)&sW[k * 64 + cg * 16 + 12];
            float2 wv[8] = { {w0.x,w0.y},{w0.z,w0.w},{w1.x,w1.y},{w1.z,w1.w},
                             {w2.x,w2.y},{w2.z,w2.w},{w3.x,w3.y},{w3.z,w3.w} };
            #pragma unroll
            for (int i = 0; i < 4; i++) {
                float2 fi = make_float2(f[i], f[i]);
                #pragma unroll
                for (int j = 0; j < 8; j++)
                    acc[i][j] = ffma2(fi, wv[j], acc[i][j]);
            }
        }
    }

    __half* pbase = g_proj + (size_t)m * NN * DH;
    #pragma unroll
    for (int i = 0; i < 4; i++) {
        int n = node0 + rg + 32 * i;
        if (n < NN) {
            __half2* prow = (__half2*)(pbase + (size_t)n * DH + cg * 16);
            union { __half2 h[4]; uint4 u; } pk0, pk1;
            #pragma unroll
            for (int j = 0; j < 4; j++)
                pk0.h[j] = __floats2half2_rn(acc[i][j].x, acc[i][j].y);
            #pragma unroll
            for (int j = 0; j < 4; j++)
                pk1.h[j] = __floats2half2_rn(acc[i][4 + j].x, acc[i][4 + j].y);
            *(uint4*)prow       = pk0.u;
            *((uint4*)prow + 1) = pk1.u;
        }
    }
}

// ---------------- E1: single-pass capacity-binned edge sort ----------------
__global__ void k_binedges(const int* __restrict__ src, const int* __restrict__ dst,
                           int m) {
    int e = blockIdx.x * blockDim.x + threadIdx.x;
    if (e >= EDGES) return;
    int s = __ldg(src + (size_t)m * EDGES + e);
    int d = __ldg(dst + (size_t)m * EDGES + e);
    long seg = (long)m * NN + d;
    int r = atomicAdd(&g_count[seg], 1);
    if (r < CAP)
        g_eidx[(size_t)seg * CAP + r] = s;
}

// ---------------- E4: per-m gather-reduce + mean + bias + prelu ------------
__global__ void k_aggregate(const float* __restrict__ b,
                            const float* __restrict__ prelu_a, int m) {
    long gt   = (long)blockIdx.x * blockDim.x + threadIdx.x;
    long nl   = gt >> 3;                    // node within m
    int  lane = (int)(gt & 7);
    if (nl >= NN) return;
    long gid = (long)m * NN + nl;

    int cnt = g_count[gid];
    int nv  = cnt < CAP ? cnt : CAP;

    const int*   ei = g_eidx + (size_t)gid * CAP;
    const uint4* pb = (const uint4*)g_proj + (size_t)m * NN * 8;
    float acc[8] = {0.f,0.f,0.f,0.f,0.f,0.f,0.f,0.f};

    int j = 0;
    for (; j + 1 < nv; j += 2) {
        int s0 = __ldg(&ei[j]);
        int s1 = __ldg(&ei[j + 1]);
        uint4 v0 = __ldg(&pb[(size_t)s0 * 8 + lane]);
        uint4 v1 = __ldg(&pb[(size_t)s1 * 8 + lane]);
        float2 f;
        f = __half22float2(*(__half2*)&v0.x); acc[0]+=f.x; acc[1]+=f.y;
        f = __half22float2(*(__half2*)&v0.y); acc[2]+=f.x; acc[3]+=f.y;
        f = __half22float2(*(__half2*)&v0.z); acc[4]+=f.x; acc[5]+=f.y;
        f = __half22float2(*(__half2*)&v0.w); acc[6]+=f.x; acc[7]+=f.y;
        f = __half22float2(*(__half2*)&v1.x); acc[0]+=f.x; acc[1]+=f.y;
        f = __half22float2(*(__half2*)&v1.y); acc[2]+=f.x; acc[3]+=f.y;
        f = __half22float2(*(__half2*)&v1.z); acc[4]+=f.x; acc[5]+=f.y;
        f = __half22float2(*(__half2*)&v1.w); acc[6]+=f.x; acc[7]+=f.y;
    }
    if (j < nv) {
        int s0 = __ldg(&ei[j]);
        uint4 v0 = __ldg(&pb[(size_t)s0 * 8 + lane]);
        float2 f;
        f = __half22float2(*(__half2*)&v0.x); acc[0]+=f.x; acc[1]+=f.y;
        f = __half22float2(*(__half2*)&v0.y); acc[2]+=f.x; acc[3]+=f.y;
        f = __half22float2(*(__half2*)&v0.z); acc[4]+=f.x; acc[5]+=f.y;
        f = __half22float2(*(__half2*)&v0.w); acc[6]+=f.x; acc[7]+=f.y;
    }

    float inv   = 1.0f / fmaxf((float)cnt, 1.0f);
    float alpha = __ldg(prelu_a + m);
    const float* bp = b + m * DH + lane * 8;
    float h[8];
    #pragma unroll
    for (int c = 0; c < 8; c++) {
        float x = acc[c] * inv + __ldg(bp + c);
        h[c] = x > 0.f ? x : alpha * x;
    }
    union { __half2 p[4]; uint4 u; } pk;
    #pragma unroll
    for (int c = 0; c < 4; c++)
        pk.p[c] = __floats2half2_rn(h[2*c], h[2*c+1]);
    ((uint4*)(g_hn + ((size_t)nl * MM + m) * DH))[lane] = pk.u;
}

// ---------------- K4: per-m logits — 256 rows/block, 8x16 thread tile ------
#define HPAD 68
__global__ __launch_bounds__(128) void k_attnlogits(const float* __restrict__ fc_W,
                                                    const float* __restrict__ fc_b,
                                                    const float* __restrict__ attn,
                                                    int m) {
    extern __shared__ float dynsm[];
    float* sH = dynsm;                 // 256 x HPAD
    float* sW = dynsm + 256 * HPAD;    // 64 x 64
    __shared__ float sPart;

    const int t = threadIdx.x;
    const int rg = t >> 2;
    const int cg = t & 3;
    const long p0 = (long)blockIdx.x * 256;

    if (t == 0) sPart = 0.f;

    #pragma unroll
    for (int it = 0; it < 16; it++) {
        int idx = t + 128 * it;
        int row = idx >> 3;
        int k8  = idx & 7;
        long n  = p0 + row;
        uint4 v = make_uint4(0u, 0u, 0u, 0u);
        if (n < NN)
            v = *((const uint4*)(g_hn + ((size_t)n * MM + m) * DH) + k8);
        float* dstp = &sH[row * HPAD + k8 * 8];
        float2 f0 = __half22float2(*(__half2*)&v.x);
        float2 f1 = __half22float2(*(__half2*)&v.y);
        float2 f2 = __half22float2(*(__half2*)&v.z);
        float2 f3 = __half22float2(*(__half2*)&v.w);
        dstp[0] = f0.x; dstp[1] = f0.y; dstp[2] = f1.x; dstp[3] = f1.y;
        dstp[4] = f2.x; dstp[5] = f2.y; dstp[6] = f3.x; dstp[7] = f3.y;
    }
    #pragma unroll
    for (int it = 0; it < 8; it++) {
        int idx = t + 128 * it;
        ((float4*)sW)[idx] = ((const float4*)fc_W)[idx];
    }
    __syncthreads();

    float2 acc[8][8];
    #pragma unroll
    for (int i = 0; i < 8; i++)
        #pragma unroll
        for (int j = 0; j < 8; j++) acc[i][j] = make_float2(0.f, 0.f);

    #pragma unroll 8
    for (int k = 0; k < DH; k++) {
        float f[8];
        #pragma unroll
        for (int i = 0; i < 8; i++) f[i] = sH[(rg + 32 * i) * HPAD + k];
        float4 w0 = *(const float4*)&sW[k * 64 + cg * 16 + 0];
        float4 w1 = *(const float4*)&sW[k * 64 + cg * 16 + 4];
        float4 w2 = *(const float4*)&sW[k * 64 + cg * 16 + 8];
        float4 w3 = *(const float4*)&sW[k * 64 + cg * 16 + 12];
        float2 wv[8] = { {w0.x,w0.y},{w0.z,w0.w},{w1.x,w1.y},{w1.z,w1.w},
                         {w2.x,w2.y},{w2.z,w2.w},{w3.x,w3.y},{w3.z,w3.w} };
        #pragma unroll
        for (int i = 0; i < 8; i++) {
            float2 fi = make_float2(f[i], f[i]);
            #pragma unroll
            for (int j = 0; j < 8; j++)
                acc[i][j] = ffma2(fi, wv[j], acc[i][j]);
        }
    }

    const float2* fb2 = (const float2*)fc_b;
    const float2* av2 = (const float2*)attn;
    float csum = 0.f;
    #pragma unroll
    for (int i = 0; i < 8; i++) {
        long n = p0 + rg + 32 * i;
        float ci = 0.f;
        #pragma unroll
        for (int j = 0; j < 8; j++) {
            float2 bb = __ldg(fb2 + cg * 8 + j);
            float2 aa = __ldg(av2 + cg * 8 + j);
            ci += tanh_hw(acc[i][j].x + bb.x) * aa.x
                + tanh_hw(acc[i][j].y + bb.y) * aa.y;
        }
        ci += __shfl_xor_sync(0xffffffffu, ci, 1);
        ci += __shfl_xor_sync(0xffffffffu, ci, 2);
        if (cg == 0 && n < NN) csum += ci;
    }
    if (cg == 0) atomicAdd(&sPart, csum);
    __syncthreads();
    if (t == 0) atomicAdd(&g_logits[m], sPart * (1.0f / (float)NN));
}

// ---------------- K5: softmax(logits) + z = sum_m beta_m * hn[:,m,:] -------
__global__ void k_combine(float* __restrict__ out) {
    const long tid = (long)blockIdx.x * blockDim.x + threadIdx.x;
    if (tid >= (long)NN * 8) return;
    const int  q = (int)(tid & 7);
    const long n = tid >> 3;

    float l0 = g_logits[0], l1 = g_logits[1], l2 = g_logits[2];
    float mx = fmaxf(l0, fmaxf(l1, l2));
    float e0 = __expf(l0 - mx), e1 = __expf(l1 - mx), e2 = __expf(l2 - mx);
    float is = 1.0f / (e0 + e1 + e2);
    float b0 = e0 * is, b1 = e1 * is, b2 = e2 * is;

    const uint4* r = (const uint4*)(g_hn + (size_t)n * (MM * DH)) + q;
    uint4 u0 = __ldg(r), u1 = __ldg(r + 8), u2 = __ldg(r + 16);

    float o[8];
    #pragma unroll
    for (int c = 0; c < 4; c++) {
        float2 f0 = __half22float2(((const __half2*)&u0)[c]);
        float2 f1 = __half22float2(((const __half2*)&u1)[c]);
        float2 f2 = __half22float2(((const __half2*)&u2)[c]);
        o[2*c]   = b0 * f0.x + b1 * f1.x + b2 * f2.x;
        o[2*c+1] = b0 * f0.y + b1 * f1.y + b2 * f2.y;
    }
    float* op = out + (size_t)n * DH + q * 8;
    *(float4*)op       = make_float4(o[0], o[1], o[2], o[3]);
    *(float4*)(op + 4) = make_float4(o[4], o[5], o[6], o[7]);
}

// ---------------- launcher: per-m pipeline across 4 streams ----------------
static cudaStream_t s1 = nullptr, s2 = nullptr, s3 = nullptr;
static cudaEvent_t  evFork = nullptr, evLog = nullptr, evDone = nullptr;
static cudaEvent_t  evSc[MM], evPj[MM], evAgg[MM];

extern "C" void kernel_launch(void* const* d_in, const int* in_sizes, int n_in,
                              void* d_out, int out_size) {
    const float* feats   = (const float*)d_in[0];
    const int*   src     = (const int*)  d_in[1];
    const int*   dst     = (const int*)  d_in[2];
    const float* W       = (const float*)d_in[3];
    const float* b       = (const float*)d_in[4];
    const float* prelu_a = (const float*)d_in[5];
    const float* fc_W    = (const float*)d_in[6];
    const float* fc_b    = (const float*)d_in[7];
    const float* attn    = (const float*)d_in[8];
    float* out = (float*)d_out;

    if (!s1) {
        cudaStreamCreateWithFlags(&s1, cudaStreamNonBlocking);
        cudaStreamCreateWithFlags(&s2, cudaStreamNonBlocking);
        cudaStreamCreateWithFlags(&s3, cudaStreamNonBlocking);
        cudaEventCreateWithFlags(&evFork, cudaEventDisableTiming);
        cudaEventCreateWithFlags(&evLog,  cudaEventDisableTiming);
        cudaEventCreateWithFlags(&evDone, cudaEventDisableTiming);
        for (int m = 0; m < MM; m++) {
            cudaEventCreateWithFlags(&evSc[m],  cudaEventDisableTiming);
            cudaEventCreateWithFlags(&evPj[m],  cudaEventDisableTiming);
            cudaEventCreateWithFlags(&evAgg[m], cudaEventDisableTiming);
        }
    }

    void *p_cnt, *p_log;
    cudaGetSymbolAddress(&p_cnt, g_count);
    cudaGetSymbolAddress(&p_log, g_logits);

    const int attn_smem = 256 * HPAD * 4 + 64 * 64 * 4;   // 86016
    cudaFuncSetAttribute(k_attnlogits,
                         cudaFuncAttributeMaxDynamicSharedMemorySize, attn_smem);

    const unsigned geb = (EDGES + 255) / 256;
    const unsigned gnb128 = (NN + 127) / 128;             // k_proj blocks (782)
    const unsigned gnb256 = (NN + 255) / 256;             // attn blocks
    const unsigned gab = (unsigned)(((long)NN * 8 + 255) / 256);

    // fork
    cudaEventRecord(evFork, 0);
    cudaStreamWaitEvent(s1, evFork, 0);

    // s1: per-m single-pass edge binning
    cudaMemsetAsync(p_cnt, 0, sizeof(int) * NSEG, s1);
    for (int m = 0; m < MM; m++) {
        k_binedges<<<geb, 256, 0, s1>>>(src, dst, m);
        cudaEventRecord(evSc[m], s1);
    }

    // s0: logits clear + per-m projection
    cudaMemsetAsync(p_log, 0, sizeof(float) * MM, 0);
    cudaEventRecord(evLog, 0);
    for (int m = 0; m < MM; m++) {
        k_proj<<<gnb128, 128>>>(feats, W, m);
        cudaEventRecord(evPj[m], 0);
    }

    // s2: per-m aggregate (after binedges_m + proj_m)
    cudaStreamWaitEvent(s2, evFork, 0);
    for (int m = 0; m < MM; m++) {
        cudaStreamWaitEvent(s2, evSc[m], 0);
        cudaStreamWaitEvent(s2, evPj[m], 0);
        k_aggregate<<<(unsigned)(((long)NN * 8 + 255) / 256), 256, 0, s2>>>(b, prelu_a, m);
        cudaEventRecord(evAgg[m], s2);
    }

    // s3: per-m attention logits (after agg_m)
    cudaStreamWaitEvent(s3, evLog, 0);
    for (int m = 0; m < MM; m++) {
        cudaStreamWaitEvent(s3, evAgg[m], 0);
        k_attnlogits<<<gnb256, 128, attn_smem, s3>>>(fc_W, fc_b, attn, m);
    }
    cudaEventRecord(evDone, s3);

    // s0: combine after everything
    cudaStreamWaitEvent(0, evDone, 0);
    k_combine<<<gab, 256>>>(out);
}

// round 11
// speedup vs baseline: 1.2596x; 1.2596x over previous
#include <cuda_runtime.h>
#include <cuda_fp16.h>
#include <cstdint>
#include <cstddef>

#define MM    3
#define NN    100000
#define DIN   128
#define DH    64
#define EDGES 1600000
#define NSEG  (MM * NN)
#define CAP   64                         // per-segment slot capacity (P(deg>64)~1e-20)

// ---------------- scratch (device globals; no allocations) ----------------
__device__ __half g_proj[(size_t)MM * NN * DH];  // 38.4 MB [m][n][h] fp16
__device__ __half g_hn  [(size_t)NN * MM * DH];  // 38.4 MB [n][m][h] fp16
__device__ int    g_count[NSEG];                 // per-(m,dst) degree
__device__ int    g_eidx[(size_t)NSEG * CAP];    // 76.8 MB binned src ids
__device__ float  g_logits[MM];

// packed f32x2 FMA (FFMA2)
__device__ __forceinline__ float2 ffma2(float2 a, float2 b, float2 c) {
    unsigned long long au = *reinterpret_cast<unsigned long long*>(&a);
    unsigned long long bu = *reinterpret_cast<unsigned long long*>(&b);
    unsigned long long cu = *reinterpret_cast<unsigned long long*>(&c);
    unsigned long long du;
    asm("fma.rn.f32x2 %0, %1, %2, %3;" : "=l"(du) : "l"(au), "l"(bu), "l"(cu));
    return *reinterpret_cast<float2*>(&du);
}

__device__ __forceinline__ float tanh_hw(float x) {
    float y;
    asm("tanh.approx.f32 %0, %1;" : "=f"(y) : "f"(x));
    return y;
}

// ---------------- K1: proj[m] = feats[m] @ W[m]  — tensor-core HMMA --------
// 128 threads = 4 warps. Block: 128 rows x 64 cols, K=128.
// smem: sA [128][136] fp16 (padded rows: bank-conflict-free fragment loads),
//       sWt [64][136] fp16, W transposed [n][k] so B frags are k-contiguous.
// Warp w: rows [w*32, w*32+32) = 2 m-tiles x 8 n-tiles of m16n8k16.
#define SAS 136                          // padded stride in halves (272 B)
__global__ __launch_bounds__(128) void k_proj(const float* __restrict__ feats,
                                              const float* __restrict__ W, int m) {
    extern __shared__ __half dynh[];
    __half* sA  = dynh;                  // 128*136 halves = 34816 B
    __half* sWt = dynh + 128 * SAS;      // 64*136 halves  = 17408 B

    const int t = threadIdx.x;
    const int node0 = blockIdx.x * 128;
    const int lane = t & 31, w = t >> 5;
    const int gid = lane >> 2, tid4 = lane & 3;

    const float* fbase = feats + (size_t)m * NN * DIN;
    const float* wbase = W     + (size_t)m * DIN * DH;

    // feats tile 128x128 fp32 -> fp16 smem (4096 float4 / 128 thr = 32 each)
    #pragma unroll
    for (int it = 0; it < 32; it++) {
        int idx = t + 128 * it;
        int row = idx >> 5;
        int c4  = idx & 31;
        int gn  = node0 + row;
        float4 v = make_float4(0.f, 0.f, 0.f, 0.f);
        if (gn < NN)
            v = *(const float4*)(fbase + (size_t)gn * DIN + c4 * 4);
        *(__half2*)&sA[row * SAS + c4 * 4]     = __floats2half2_rn(v.x, v.y);
        *(__half2*)&sA[row * SAS + c4 * 4 + 2] = __floats2half2_rn(v.z, v.w);
    }
    // W 128x64 fp32 -> sWt[n][k] fp16 (8192 / 128 thr = 64 each, coalesced reads)
    #pragma unroll
    for (int it = 0; it < 64; it++) {
        int idx = t + 128 * it;
        int k = idx >> 6;
        int n = idx & 63;
        sWt[n * SAS + k] = __float2half_rn(wbase[(size_t)k * DH + n]);
    }
    __syncthreads();

    float c[2][8][4];
    #pragma unroll
    for (int mt = 0; mt < 2; mt++)
        #pragma unroll
        for (int nt = 0; nt < 8; nt++)
            #pragma unroll
            for (int q = 0; q < 4; q++) c[mt][nt][q] = 0.f;

    #pragma unroll
    for (int ks = 0; ks < 8; ks++) {
        const int k0 = ks * 16;
        uint32_t a[2][4];
        #pragma unroll
        for (int mt = 0; mt < 2; mt++) {
            int r = w * 32 + mt * 16 + gid;
            a[mt][0] = *(const uint32_t*)&sA[r * SAS + k0 + tid4 * 2];
            a[mt][1] = *(const uint32_t*)&sA[(r + 8) * SAS + k0 + tid4 * 2];
            a[mt][2] = *(const uint32_t*)&sA[r * SAS + k0 + tid4 * 2 + 8];
            a[mt][3] = *(const uint32_t*)&sA[(r + 8) * SAS + k0 + tid4 * 2 + 8];
        }
        #pragma unroll
        for (int nt = 0; nt < 8; nt++) {
            int n = nt * 8 + gid;
            uint32_t b0 = *(const uint32_t*)&sWt[n * SAS + k0 + tid4 * 2];
            uint32_t b1 = *(const uint32_t*)&sWt[n * SAS + k0 + tid4 * 2 + 8];
            #pragma unroll
            for (int mt = 0; mt < 2; mt++) {
                asm volatile(
                    "mma.sync.aligned.m16n8k16.row.col.f32.f16.f16.f32 "
                    "{%0,%1,%2,%3}, {%4,%5,%6,%7}, {%8,%9}, {%0,%1,%2,%3};"
                    : "+f"(c[mt][nt][0]), "+f"(c[mt][nt][1]),
                      "+f"(c[mt][nt][2]), "+f"(c[mt][nt][3])
                    : "r"(a[mt][0]), "r"(a[mt][1]), "r"(a[mt][2]), "r"(a[mt][3]),
                      "r"(b0), "r"(b1));
            }
        }
    }

    // store fp16 proj: c0,c1 = (r, col..col+1); c2,c3 = (r+8, col..col+1)
    __half* pbase = g_proj + (size_t)m * NN * DH;
    #pragma unroll
    for (int mt = 0; mt < 2; mt++) {
        int r0 = node0 + w * 32 + mt * 16 + gid;
        #pragma unroll
        for (int nt = 0; nt < 8; nt++) {
            int col = nt * 8 + tid4 * 2;
            if (r0 < NN)
                *(__half2*)(pbase + (size_t)r0 * DH + col) =
                    __floats2half2_rn(c[mt][nt][0], c[mt][nt][1]);
            if (r0 + 8 < NN)
                *(__half2*)(pbase + (size_t)(r0 + 8) * DH + col) =
                    __floats2half2_rn(c[mt][nt][2], c[mt][nt][3]);
        }
    }
}
#define PROJ_SMEM ((128 + 64) * SAS * 2)   // 52224 B

// ---------------- E1: single-pass capacity-binned edge sort ----------------
__global__ void k_binedges(const int* __restrict__ src, const int* __restrict__ dst,
                           int m) {
    int e = blockIdx.x * blockDim.x + threadIdx.x;
    if (e >= EDGES) return;
    int s = __ldg(src + (size_t)m * EDGES + e);
    int d = __ldg(dst + (size_t)m * EDGES + e);
    long seg = (long)m * NN + d;
    int r = atomicAdd(&g_count[seg], 1);
    if (r < CAP)
        g_eidx[(size_t)seg * CAP + r] = s;
}

// ---------------- E4: per-m gather-reduce + mean + bias + prelu ------------
__global__ void k_aggregate(const float* __restrict__ b,
                            const float* __restrict__ prelu_a, int m) {
    long gt   = (long)blockIdx.x * blockDim.x + threadIdx.x;
    long nl   = gt >> 3;                    // node within m
    int  lane = (int)(gt & 7);
    if (nl >= NN) return;
    long gid = (long)m * NN + nl;

    int cnt = g_count[gid];
    int nv  = cnt < CAP ? cnt : CAP;

    const int*   ei = g_eidx + (size_t)gid * CAP;
    const uint4* pb = (const uint4*)g_proj + (size_t)m * NN * 8;
    float acc[8] = {0.f,0.f,0.f,0.f,0.f,0.f,0.f,0.f};

    int j = 0;
    for (; j + 1 < nv; j += 2) {
        int s0 = __ldg(&ei[j]);
        int s1 = __ldg(&ei[j + 1]);
        uint4 v0 = __ldg(&pb[(size_t)s0 * 8 + lane]);
        uint4 v1 = __ldg(&pb[(size_t)s1 * 8 + lane]);
        float2 f;
        f = __half22float2(*(__half2*)&v0.x); acc[0]+=f.x; acc[1]+=f.y;
        f = __half22float2(*(__half2*)&v0.y); acc[2]+=f.x; acc[3]+=f.y;
        f = __half22float2(*(__half2*)&v0.z); acc[4]+=f.x; acc[5]+=f.y;
        f = __half22float2(*(__half2*)&v0.w); acc[6]+=f.x; acc[7]+=f.y;
        f = __half22float2(*(__half2*)&v1.x); acc[0]+=f.x; acc[1]+=f.y;
        f = __half22float2(*(__half2*)&v1.y); acc[2]+=f.x; acc[3]+=f.y;
        f = __half22float2(*(__half2*)&v1.z); acc[4]+=f.x; acc[5]+=f.y;
        f = __half22float2(*(__half2*)&v1.w); acc[6]+=f.x; acc[7]+=f.y;
    }
    if (j < nv) {
        int s0 = __ldg(&ei[j]);
        uint4 v0 = __ldg(&pb[(size_t)s0 * 8 + lane]);
        float2 f;
        f = __half22float2(*(__half2*)&v0.x); acc[0]+=f.x; acc[1]+=f.y;
        f = __half22float2(*(__half2*)&v0.y); acc[2]+=f.x; acc[3]+=f.y;
        f = __half22float2(*(__half2*)&v0.z); acc[4]+=f.x; acc[5]+=f.y;
        f = __half22float2(*(__half2*)&v0.w); acc[6]+=f.x; acc[7]+=f.y;
    }

    float inv   = 1.0f / fmaxf((float)cnt, 1.0f);
    float alpha = __ldg(prelu_a + m);
    const float* bp = b + m * DH + lane * 8;
    float h[8];
    #pragma unroll
    for (int c = 0; c < 8; c++) {
        float x = acc[c] * inv + __ldg(bp + c);
        h[c] = x > 0.f ? x : alpha * x;
    }
    union { __half2 p[4]; uint4 u; } pk;
    #pragma unroll
    for (int c = 0; c < 4; c++)
        pk.p[c] = __floats2half2_rn(h[2*c], h[2*c+1]);
    ((uint4*)(g_hn + ((size_t)nl * MM + m) * DH))[lane] = pk.u;
}

// ---------------- K4: per-m logits — 256 rows/block, 8x16 thread tile ------
#define HPAD 68
__global__ __launch_bounds__(128) void k_attnlogits(const float* __restrict__ fc_W,
                                                    const float* __restrict__ fc_b,
                                                    const float* __restrict__ attn,
                                                    int m) {
    extern __shared__ float dynsm[];
    float* sH = dynsm;                 // 256 x HPAD
    float* sW = dynsm + 256 * HPAD;    // 64 x 64
    __shared__ float sPart;

    const int t = threadIdx.x;
    const int rg = t >> 2;
    const int cg = t & 3;
    const long p0 = (long)blockIdx.x * 256;

    if (t == 0) sPart = 0.f;

    #pragma unroll
    for (int it = 0; it < 16; it++) {
        int idx = t + 128 * it;
        int row = idx >> 3;
        int k8  = idx & 7;
        long n  = p0 + row;
        uint4 v = make_uint4(0u, 0u, 0u, 0u);
        if (n < NN)
            v = *((const uint4*)(g_hn + ((size_t)n * MM + m) * DH) + k8);
        float* dstp = &sH[row * HPAD + k8 * 8];
        float2 f0 = __half22float2(*(__half2*)&v.x);
        float2 f1 = __half22float2(*(__half2*)&v.y);
        float2 f2 = __half22float2(*(__half2*)&v.z);
        float2 f3 = __half22float2(*(__half2*)&v.w);
        dstp[0] = f0.x; dstp[1] = f0.y; dstp[2] = f1.x; dstp[3] = f1.y;
        dstp[4] = f2.x; dstp[5] = f2.y; dstp[6] = f3.x; dstp[7] = f3.y;
    }
    #pragma unroll
    for (int it = 0; it < 8; it++) {
        int idx = t + 128 * it;
        ((float4*)sW)[idx] = ((const float4*)fc_W)[idx];
    }
    __syncthreads();

    float2 acc[8][8];
    #pragma unroll
    for (int i = 0; i < 8; i++)
        #pragma unroll
        for (int j = 0; j < 8; j++) acc[i][j] = make_float2(0.f, 0.f);

    #pragma unroll 8
    for (int k = 0; k < DH; k++) {
        float f[8];
        #pragma unroll
        for (int i = 0; i < 8; i++) f[i] = sH[(rg + 32 * i) * HPAD + k];
        float4 w0 = *(const float4*)&sW[k * 64 + cg * 16 + 0];
        float4 w1 = *(const float4*)&sW[k * 64 + cg * 16 + 4];
        float4 w2 = *(const float4*)&sW[k * 64 + cg * 16 + 8];
        float4 w3 = *(const float4*)&sW[k * 64 + cg * 16 + 12];
        float2 wv[8] = { {w0.x,w0.y},{w0.z,w0.w},{w1.x,w1.y},{w1.z,w1.w},
                         {w2.x,w2.y},{w2.z,w2.w},{w3.x,w3.y},{w3.z,w3.w} };
        #pragma unroll
        for (int i = 0; i < 8; i++) {
            float2 fi = make_float2(f[i], f[i]);
            #pragma unroll
            for (int j = 0; j < 8; j++)
                acc[i][j] = ffma2(fi, wv[j], acc[i][j]);
        }
    }

    const float2* fb2 = (const float2*)fc_b;
    const float2* av2 = (const float2*)attn;
    float csum = 0.f;
    #pragma unroll
    for (int i = 0; i < 8; i++) {
        long n = p0 + rg + 32 * i;
        float ci = 0.f;
        #pragma unroll
        for (int j = 0; j < 8; j++) {
            float2 bb = __ldg(fb2 + cg * 8 + j);
            float2 aa = __ldg(av2 + cg * 8 + j);
            ci += tanh_hw(acc[i][j].x + bb.x) * aa.x
                + tanh_hw(acc[i][j].y + bb.y) * aa.y;
        }
        ci += __shfl_xor_sync(0xffffffffu, ci, 1);
        ci += __shfl_xor_sync(0xffffffffu, ci, 2);
        if (cg == 0 && n < NN) csum += ci;
    }
    if (cg == 0) atomicAdd(&sPart, csum);
    __syncthreads();
    if (t == 0) atomicAdd(&g_logits[m], sPart * (1.0f / (float)NN));
}

// ---------------- K5: softmax(logits) + z = sum_m beta_m * hn[:,m,:] -------
__global__ void k_combine(float* __restrict__ out) {
    const long tid = (long)blockIdx.x * blockDim.x + threadIdx.x;
    if (tid >= (long)NN * 8) return;
    const int  q = (int)(tid & 7);
    const long n = tid >> 3;

    float l0 = g_logits[0], l1 = g_logits[1], l2 = g_logits[2];
    float mx = fmaxf(l0, fmaxf(l1, l2));
    float e0 = __expf(l0 - mx), e1 = __expf(l1 - mx), e2 = __expf(l2 - mx);
    float is = 1.0f / (e0 + e1 + e2);
    float b0 = e0 * is, b1 = e1 * is, b2 = e2 * is;

    const uint4* r = (const uint4*)(g_hn + (size_t)n * (MM * DH)) + q;
    uint4 u0 = __ldg(r), u1 = __ldg(r + 8), u2 = __ldg(r + 16);

    float o[8];
    #pragma unroll
    for (int c = 0; c < 4; c++) {
        float2 f0 = __half22float2(((const __half2*)&u0)[c]);
        float2 f1 = __half22float2(((const __half2*)&u1)[c]);
        float2 f2 = __half22float2(((const __half2*)&u2)[c]);
        o[2*c]   = b0 * f0.x + b1 * f1.x + b2 * f2.x;
        o[2*c+1] = b0 * f0.y + b1 * f1.y + b2 * f2.y;
    }
    float* op = out + (size_t)n * DH + q * 8;
    *(float4*)op       = make_float4(o[0], o[1], o[2], o[3]);
    *(float4*)(op + 4) = make_float4(o[4], o[5], o[6], o[7]);
}

// ---------------- launcher: per-m pipeline across 4 streams ----------------
static cudaStream_t s1 = nullptr, s2 = nullptr, s3 = nullptr;
static cudaEvent_t  evFork = nullptr, evLog = nullptr, evDone = nullptr;
static cudaEvent_t  evSc[MM], evPj[MM], evAgg[MM];

extern "C" void kernel_launch(void* const* d_in, const int* in_sizes, int n_in,
                              void* d_out, int out_size) {
    const float* feats   = (const float*)d_in[0];
    const int*   src     = (const int*)  d_in[1];
    const int*   dst     = (const int*)  d_in[2];
    const float* W       = (const float*)d_in[3];
    const float* b       = (const float*)d_in[4];
    const float* prelu_a = (const float*)d_in[5];
    const float* fc_W    = (const float*)d_in[6];
    const float* fc_b    = (const float*)d_in[7];
    const float* attn    = (const float*)d_in[8];
    float* out = (float*)d_out;

    if (!s1) {
        cudaStreamCreateWithFlags(&s1, cudaStreamNonBlocking);
        cudaStreamCreateWithFlags(&s2, cudaStreamNonBlocking);
        cudaStreamCreateWithFlags(&s3, cudaStreamNonBlocking);
        cudaEventCreateWithFlags(&evFork, cudaEventDisableTiming);
        cudaEventCreateWithFlags(&evLog,  cudaEventDisableTiming);
        cudaEventCreateWithFlags(&evDone, cudaEventDisableTiming);
        for (int m = 0; m < MM; m++) {
            cudaEventCreateWithFlags(&evSc[m],  cudaEventDisableTiming);
            cudaEventCreateWithFlags(&evPj[m],  cudaEventDisableTiming);
            cudaEventCreateWithFlags(&evAgg[m], cudaEventDisableTiming);
        }
    }

    void *p_cnt, *p_log;
    cudaGetSymbolAddress(&p_cnt, g_count);
    cudaGetSymbolAddress(&p_log, g_logits);

    const int attn_smem = 256 * HPAD * 4 + 64 * 64 * 4;   // 86016
    cudaFuncSetAttribute(k_attnlogits,
                         cudaFuncAttributeMaxDynamicSharedMemorySize, attn_smem);
    cudaFuncSetAttribute(k_proj,
                         cudaFuncAttributeMaxDynamicSharedMemorySize, PROJ_SMEM);

    const unsigned geb = (EDGES + 255) / 256;
    const unsigned gnb128 = (NN + 127) / 128;             // k_proj blocks (782)
    const unsigned gnb256 = (NN + 255) / 256;             // attn blocks
    const unsigned gab = (unsigned)(((long)NN * 8 + 255) / 256);

    // fork
    cudaEventRecord(evFork, 0);
    cudaStreamWaitEvent(s1, evFork, 0);

    // s1: per-m single-pass edge binning
    cudaMemsetAsync(p_cnt, 0, sizeof(int) * NSEG, s1);
    for (int m = 0; m < MM; m++) {
        k_binedges<<<geb, 256, 0, s1>>>(src, dst, m);
        cudaEventRecord(evSc[m], s1);
    }

    // s0: logits clear + per-m projection (tensor-core)
    cudaMemsetAsync(p_log, 0, sizeof(float) * MM, 0);
    cudaEventRecord(evLog, 0);
    for (int m = 0; m < MM; m++) {
        k_proj<<<gnb128, 128, PROJ_SMEM>>>(feats, W, m);
        cudaEventRecord(evPj[m], 0);
    }

    // s2: per-m aggregate (after binedges_m + proj_m)
    cudaStreamWaitEvent(s2, evFork, 0);
    for (int m = 0; m < MM; m++) {
        cudaStreamWaitEvent(s2, evSc[m], 0);
        cudaStreamWaitEvent(s2, evPj[m], 0);
        k_aggregate<<<(unsigned)(((long)NN * 8 + 255) / 256), 256, 0, s2>>>(b, prelu_a, m);
        cudaEventRecord(evAgg[m], s2);
    }

    // s3: per-m attention logits (after agg_m)
    cudaStreamWaitEvent(s3, evLog, 0);
    for (int m = 0; m < MM; m++) {
        cudaStreamWaitEvent(s3, evAgg[m], 0);
        k_attnlogits<<<gnb256, 128, attn_smem, s3>>>(fc_W, fc_b, attn, m);
    }
    cudaEventRecord(evDone, s3);

    // s0: combine after everything
    cudaStreamWaitEvent(0, evDone, 0);
    k_combine<<<gab, 256>>>(out);
}

// round 12
// speedup vs baseline: 1.3725x; 1.0897x over previous
#include <cuda_runtime.h>
#include <cuda_fp16.h>
#include <cstdint>
#include <cstddef>

#define MM    3
#define NN    100000
#define DIN   128
#define DH    64
#define EDGES 1600000
#define NSEG  (MM * NN)
#define CAP   64                         // per-segment slot capacity (P(deg>64)~1e-20)

// ---------------- scratch (device globals; no allocations) ----------------
__device__ __half g_proj[(size_t)MM * NN * DH];  // 38.4 MB [m][n][h] fp16
__device__ __half g_hn  [(size_t)NN * MM * DH];  // 38.4 MB [n][m][h] fp16
__device__ int    g_count[NSEG];                 // per-(m,dst) degree
__device__ int    g_eidx[(size_t)NSEG * CAP];    // 76.8 MB binned src ids
__device__ float  g_logits[MM];

__device__ __forceinline__ float tanh_hw(float x) {
    float y;
    asm("tanh.approx.f32 %0, %1;" : "=f"(y) : "f"(x));
    return y;
}

// ---------------- K1: proj[m] = feats[m] @ W[m]  — tensor-core HMMA --------
#define SAS 136                          // padded stride in halves (272 B)
__global__ __launch_bounds__(128) void k_proj(const float* __restrict__ feats,
                                              const float* __restrict__ W, int m) {
    extern __shared__ __half dynh[];
    __half* sA  = dynh;                  // 128*136 halves = 34816 B
    __half* sWt = dynh + 128 * SAS;      // 64*136 halves  = 17408 B

    const int t = threadIdx.x;
    const int node0 = blockIdx.x * 128;
    const int lane = t & 31, w = t >> 5;
    const int gid = lane >> 2, tid4 = lane & 3;

    const float* fbase = feats + (size_t)m * NN * DIN;
    const float* wbase = W     + (size_t)m * DIN * DH;

    #pragma unroll
    for (int it = 0; it < 32; it++) {
        int idx = t + 128 * it;
        int row = idx >> 5;
        int c4  = idx & 31;
        int gn  = node0 + row;
        float4 v = make_float4(0.f, 0.f, 0.f, 0.f);
        if (gn < NN)
            v = *(const float4*)(fbase + (size_t)gn * DIN + c4 * 4);
        *(__half2*)&sA[row * SAS + c4 * 4]     = __floats2half2_rn(v.x, v.y);
        *(__half2*)&sA[row * SAS + c4 * 4 + 2] = __floats2half2_rn(v.z, v.w);
    }
    #pragma unroll
    for (int it = 0; it < 64; it++) {
        int idx = t + 128 * it;
        int k = idx >> 6;
        int n = idx & 63;
        sWt[n * SAS + k] = __float2half_rn(wbase[(size_t)k * DH + n]);
    }
    __syncthreads();

    float c[2][8][4];
    #pragma unroll
    for (int mt = 0; mt < 2; mt++)
        #pragma unroll
        for (int nt = 0; nt < 8; nt++)
            #pragma unroll
            for (int q = 0; q < 4; q++) c[mt][nt][q] = 0.f;

    #pragma unroll
    for (int ks = 0; ks < 8; ks++) {
        const int k0 = ks * 16;
        uint32_t a[2][4];
        #pragma unroll
        for (int mt = 0; mt < 2; mt++) {
            int r = w * 32 + mt * 16 + gid;
            a[mt][0] = *(const uint32_t*)&sA[r * SAS + k0 + tid4 * 2];
            a[mt][1] = *(const uint32_t*)&sA[(r + 8) * SAS + k0 + tid4 * 2];
            a[mt][2] = *(const uint32_t*)&sA[r * SAS + k0 + tid4 * 2 + 8];
            a[mt][3] = *(const uint32_t*)&sA[(r + 8) * SAS + k0 + tid4 * 2 + 8];
        }
        #pragma unroll
        for (int nt = 0; nt < 8; nt++) {
            int n = nt * 8 + gid;
            uint32_t b0 = *(const uint32_t*)&sWt[n * SAS + k0 + tid4 * 2];
            uint32_t b1 = *(const uint32_t*)&sWt[n * SAS + k0 + tid4 * 2 + 8];
            #pragma unroll
            for (int mt = 0; mt < 2; mt++) {
                asm volatile(
                    "mma.sync.aligned.m16n8k16.row.col.f32.f16.f16.f32 "
                    "{%0,%1,%2,%3}, {%4,%5,%6,%7}, {%8,%9}, {%0,%1,%2,%3};"
                    : "+f"(c[mt][nt][0]), "+f"(c[mt][nt][1]),
                      "+f"(c[mt][nt][2]), "+f"(c[mt][nt][3])
                    : "r"(a[mt][0]), "r"(a[mt][1]), "r"(a[mt][2]), "r"(a[mt][3]),
                      "r"(b0), "r"(b1));
            }
        }
    }

    __half* pbase = g_proj + (size_t)m * NN * DH;
    #pragma unroll
    for (int mt = 0; mt < 2; mt++) {
        int r0 = node0 + w * 32 + mt * 16 + gid;
        #pragma unroll
        for (int nt = 0; nt < 8; nt++) {
            int col = nt * 8 + tid4 * 2;
            if (r0 < NN)
                *(__half2*)(pbase + (size_t)r0 * DH + col) =
                    __floats2half2_rn(c[mt][nt][0], c[mt][nt][1]);
            if (r0 + 8 < NN)
                *(__half2*)(pbase + (size_t)(r0 + 8) * DH + col) =
                    __floats2half2_rn(c[mt][nt][2], c[mt][nt][3]);
        }
    }
}
#define PROJ_SMEM ((128 + 64) * SAS * 2)   // 52224 B

// ---------------- E1: single-pass capacity-binned edge sort ----------------
__global__ void k_binedges(const int* __restrict__ src, const int* __restrict__ dst,
                           int m) {
    int e = blockIdx.x * blockDim.x + threadIdx.x;
    if (e >= EDGES) return;
    int s = __ldg(src + (size_t)m * EDGES + e);
    int d = __ldg(dst + (size_t)m * EDGES + e);
    long seg = (long)m * NN + d;
    int r = atomicAdd(&g_count[seg], 1);
    if (r < CAP)
        g_eidx[(size_t)seg * CAP + r] = s;
}

// ---------------- E4: per-m gather-reduce + mean + bias + prelu ------------
__global__ void k_aggregate(const float* __restrict__ b,
                            const float* __restrict__ prelu_a, int m) {
    long gt   = (long)blockIdx.x * blockDim.x + threadIdx.x;
    long nl   = gt >> 3;                    // node within m
    int  lane = (int)(gt & 7);
    if (nl >= NN) return;
    long gid = (long)m * NN + nl;

    int cnt = g_count[gid];
    int nv  = cnt < CAP ? cnt : CAP;

    const int*   ei = g_eidx + (size_t)gid * CAP;
    const uint4* pb = (const uint4*)g_proj + (size_t)m * NN * 8;
    float acc[8] = {0.f,0.f,0.f,0.f,0.f,0.f,0.f,0.f};

    int j = 0;
    for (; j + 1 < nv; j += 2) {
        int s0 = __ldg(&ei[j]);
        int s1 = __ldg(&ei[j + 1]);
        uint4 v0 = __ldg(&pb[(size_t)s0 * 8 + lane]);
        uint4 v1 = __ldg(&pb[(size_t)s1 * 8 + lane]);
        float2 f;
        f = __half22float2(*(__half2*)&v0.x); acc[0]+=f.x; acc[1]+=f.y;
        f = __half22float2(*(__half2*)&v0.y); acc[2]+=f.x; acc[3]+=f.y;
        f = __half22float2(*(__half2*)&v0.z); acc[4]+=f.x; acc[5]+=f.y;
        f = __half22float2(*(__half2*)&v0.w); acc[6]+=f.x; acc[7]+=f.y;
        f = __half22float2(*(__half2*)&v1.x); acc[0]+=f.x; acc[1]+=f.y;
        f = __half22float2(*(__half2*)&v1.y); acc[2]+=f.x; acc[3]+=f.y;
        f = __half22float2(*(__half2*)&v1.z); acc[4]+=f.x; acc[5]+=f.y;
        f = __half22float2(*(__half2*)&v1.w); acc[6]+=f.x; acc[7]+=f.y;
    }
    if (j < nv) {
        int s0 = __ldg(&ei[j]);
        uint4 v0 = __ldg(&pb[(size_t)s0 * 8 + lane]);
        float2 f;
        f = __half22float2(*(__half2*)&v0.x); acc[0]+=f.x; acc[1]+=f.y;
        f = __half22float2(*(__half2*)&v0.y); acc[2]+=f.x; acc[3]+=f.y;
        f = __half22float2(*(__half2*)&v0.z); acc[4]+=f.x; acc[5]+=f.y;
        f = __half22float2(*(__half2*)&v0.w); acc[6]+=f.x; acc[7]+=f.y;
    }

    float inv   = 1.0f / fmaxf((float)cnt, 1.0f);
    float alpha = __ldg(prelu_a + m);
    const float* bp = b + m * DH + lane * 8;
    float h[8];
    #pragma unroll
    for (int c = 0; c < 8; c++) {
        float x = acc[c] * inv + __ldg(bp + c);
        h[c] = x > 0.f ? x : alpha * x;
    }
    union { __half2 p[4]; uint4 u; } pk;
    #pragma unroll
    for (int c = 0; c < 4; c++)
        pk.p[c] = __floats2half2_rn(h[2*c], h[2*c+1]);
    ((uint4*)(g_hn + ((size_t)nl * MM + m) * DH))[lane] = pk.u;
}

// ---------------- K4: per-m logits via HMMA -------------------------------
// 128 threads = 4 warps; block = 128 hn rows x 64 cols, K=64 (4 k-steps).
// A = hn tile (fp16 already), B = fc_W^T fp16. Epilogue: tanh_hw + attn dot.
#define ASTR 72                          // 144-B padded row stride (halves)
__global__ __launch_bounds__(128) void k_attnlogits(const float* __restrict__ fc_W,
                                                    const float* __restrict__ fc_b,
                                                    const float* __restrict__ attn,
                                                    int m) {
    __shared__ __half sA [128 * ASTR];   // 18432 B
    __shared__ __half sWt[64 * ASTR];    //  9216 B
    __shared__ float sPart;

    const int t = threadIdx.x;
    const int node0 = blockIdx.x * 128;
    const int lane = t & 31, w = t >> 5;
    const int gid = lane >> 2, tid4 = lane & 3;

    if (t == 0) sPart = 0.f;

    // hn tile: 128 rows x 8 uint4 = 1024 / 128 thr = 8 each (16B-aligned: 144B row)
    #pragma unroll
    for (int it = 0; it < 8; it++) {
        int idx = t + 128 * it;
        int row = idx >> 3;
        int k8  = idx & 7;
        int n   = node0 + row;
        uint4 v = make_uint4(0u, 0u, 0u, 0u);
        if (n < NN)
            v = *((const uint4*)(g_hn + ((size_t)n * MM + m) * DH) + k8);
        *(uint4*)&sA[row * ASTR + k8 * 8] = v;
    }
    // fc_W [k][n] fp32 -> sWt[n][k] fp16: 4096 / 128 thr = 32 each
    #pragma unroll
    for (int it = 0; it < 32; it++) {
        int idx = t + 128 * it;
        int k = idx >> 6;
        int n = idx & 63;
        sWt[n * ASTR + k] = __float2half_rn(fc_W[(size_t)k * DH + n]);
    }
    __syncthreads();

    float c[2][8][4];
    #pragma unroll
    for (int mt = 0; mt < 2; mt++)
        #pragma unroll
        for (int nt = 0; nt < 8; nt++)
            #pragma unroll
            for (int q = 0; q < 4; q++) c[mt][nt][q] = 0.f;

    #pragma unroll
    for (int ks = 0; ks < 4; ks++) {
        const int k0 = ks * 16;
        uint32_t a[2][4];
        #pragma unroll
        for (int mt = 0; mt < 2; mt++) {
            int r = w * 32 + mt * 16 + gid;
            a[mt][0] = *(const uint32_t*)&sA[r * ASTR + k0 + tid4 * 2];
            a[mt][1] = *(const uint32_t*)&sA[(r + 8) * ASTR + k0 + tid4 * 2];
            a[mt][2] = *(const uint32_t*)&sA[r * ASTR + k0 + tid4 * 2 + 8];
            a[mt][3] = *(const uint32_t*)&sA[(r + 8) * ASTR + k0 + tid4 * 2 + 8];
        }
        #pragma unroll
        for (int nt = 0; nt < 8; nt++) {
            int n = nt * 8 + gid;
            uint32_t b0 = *(const uint32_t*)&sWt[n * ASTR + k0 + tid4 * 2];
            uint32_t b1 = *(const uint32_t*)&sWt[n * ASTR + k0 + tid4 * 2 + 8];
            #pragma unroll
            for (int mt = 0; mt < 2; mt++) {
                asm volatile(
                    "mma.sync.aligned.m16n8k16.row.col.f32.f16.f16.f32 "
                    "{%0,%1,%2,%3}, {%4,%5,%6,%7}, {%8,%9}, {%0,%1,%2,%3};"
                    : "+f"(c[mt][nt][0]), "+f"(c[mt][nt][1]),
                      "+f"(c[mt][nt][2]), "+f"(c[mt][nt][3])
                    : "r"(a[mt][0]), "r"(a[mt][1]), "r"(a[mt][2]), "r"(a[mt][3]),
                      "r"(b0), "r"(b1));
            }
        }
    }

    // epilogue: tanh + attn dot, masked by row validity
    float csum = 0.f;
    #pragma unroll
    for (int mt = 0; mt < 2; mt++) {
        int r0 = node0 + w * 32 + mt * 16 + gid;
        bool ok0 = r0 < NN, ok1 = (r0 + 8) < NN;
        #pragma unroll
        for (int nt = 0; nt < 8; nt++) {
            int col = nt * 8 + tid4 * 2;
            float a0 = __ldg(attn + col),   a1 = __ldg(attn + col + 1);
            float bb0 = __ldg(fc_b + col),  bb1 = __ldg(fc_b + col + 1);
            if (ok0)
                csum += tanh_hw(c[mt][nt][0] + bb0) * a0
                      + tanh_hw(c[mt][nt][1] + bb1) * a1;
            if (ok1)
                csum += tanh_hw(c[mt][nt][2] + bb0) * a0
                      + tanh_hw(c[mt][nt][3] + bb1) * a1;
        }
    }
    // warp reduce then one atomic per warp
    #pragma unroll
    for (int o = 16; o > 0; o >>= 1)
        csum += __shfl_xor_sync(0xffffffffu, csum, o);
    if (lane == 0) atomicAdd(&sPart, csum);
    __syncthreads();
    if (t == 0) atomicAdd(&g_logits[m], sPart * (1.0f / (float)NN));
}

// ---------------- K5: softmax(logits) + z = sum_m beta_m * hn[:,m,:] -------
__global__ void k_combine(float* __restrict__ out) {
    const long tid = (long)blockIdx.x * blockDim.x + threadIdx.x;
    if (tid >= (long)NN * 8) return;
    const int  q = (int)(tid & 7);
    const long n = tid >> 3;

    float l0 = g_logits[0], l1 = g_logits[1], l2 = g_logits[2];
    float mx = fmaxf(l0, fmaxf(l1, l2));
    float e0 = __expf(l0 - mx), e1 = __expf(l1 - mx), e2 = __expf(l2 - mx);
    float is = 1.0f / (e0 + e1 + e2);
    float b0 = e0 * is, b1 = e1 * is, b2 = e2 * is;

    const uint4* r = (const uint4*)(g_hn + (size_t)n * (MM * DH)) + q;
    uint4 u0 = __ldg(r), u1 = __ldg(r + 8), u2 = __ldg(r + 16);

    float o[8];
    #pragma unroll
    for (int c = 0; c < 4; c++) {
        float2 f0 = __half22float2(((const __half2*)&u0)[c]);
        float2 f1 = __half22float2(((const __half2*)&u1)[c]);
        float2 f2 = __half22float2(((const __half2*)&u2)[c]);
        o[2*c]   = b0 * f0.x + b1 * f1.x + b2 * f2.x;
        o[2*c+1] = b0 * f0.y + b1 * f1.y + b2 * f2.y;
    }
    float* op = out + (size_t)n * DH + q * 8;
    *(float4*)op       = make_float4(o[0], o[1], o[2], o[3]);
    *(float4*)(op + 4) = make_float4(o[4], o[5], o[6], o[7]);
}

// ---------------- launcher: 3 per-m chain streams + proj stream ------------
static cudaStream_t sc[MM] = {nullptr, nullptr, nullptr};
static cudaEvent_t  evFork = nullptr;
static cudaEvent_t  evPj[MM], evAt[MM];

extern "C" void kernel_launch(void* const* d_in, const int* in_sizes, int n_in,
                              void* d_out, int out_size) {
    const float* feats   = (const float*)d_in[0];
    const int*   src     = (const int*)  d_in[1];
    const int*   dst     = (const int*)  d_in[2];
    const float* W       = (const float*)d_in[3];
    const float* b       = (const float*)d_in[4];
    const float* prelu_a = (const float*)d_in[5];
    const float* fc_W    = (const float*)d_in[6];
    const float* fc_b    = (const float*)d_in[7];
    const float* attn    = (const float*)d_in[8];
    float* out = (float*)d_out;

    if (!sc[0]) {
        for (int m = 0; m < MM; m++) {
            cudaStreamCreateWithFlags(&sc[m], cudaStreamNonBlocking);
            cudaEventCreateWithFlags(&evPj[m], cudaEventDisableTiming);
            cudaEventCreateWithFlags(&evAt[m], cudaEventDisableTiming);
        }
        cudaEventCreateWithFlags(&evFork, cudaEventDisableTiming);
    }

    void *p_cnt, *p_log;
    cudaGetSymbolAddress(&p_cnt, g_count);
    cudaGetSymbolAddress(&p_log, g_logits);

    cudaFuncSetAttribute(k_proj,
                         cudaFuncAttributeMaxDynamicSharedMemorySize, PROJ_SMEM);

    const unsigned geb = (EDGES + 255) / 256;
    const unsigned gnb = (NN + 127) / 128;                // 782 blocks
    const unsigned gagg = (unsigned)(((long)NN * 8 + 255) / 256);
    const unsigned gab = (unsigned)(((long)NN * 8 + 255) / 256);

    // s0: clear count + logits, then fork
    cudaMemsetAsync(p_cnt, 0, sizeof(int) * NSEG, 0);
    cudaMemsetAsync(p_log, 0, sizeof(float) * MM, 0);
    cudaEventRecord(evFork, 0);

    // s0: per-m projection (tensor-core), signal each
    for (int m = 0; m < MM; m++) {
        k_proj<<<gnb, 128, PROJ_SMEM>>>(feats, W, m);
        cudaEventRecord(evPj[m], 0);
    }

    // chain m on stream sc[m]: binedges -> (wait proj_m) -> aggregate -> attn
    for (int m = 0; m < MM; m++) {
        cudaStreamWaitEvent(sc[m], evFork, 0);
        k_binedges<<<geb, 256, 0, sc[m]>>>(src, dst, m);
        cudaStreamWaitEvent(sc[m], evPj[m], 0);
        k_aggregate<<<gagg, 256, 0, sc[m]>>>(b, prelu_a, m);
        k_attnlogits<<<gnb, 128, 0, sc[m]>>>(fc_W, fc_b, attn, m);
        cudaEventRecord(evAt[m], sc[m]);
    }

    // s0: combine after all chains
    for (int m = 0; m < MM; m++)
        cudaStreamWaitEvent(0, evAt[m], 0);
    k_combine<<<gab, 256>>>(out);
}

// round 14
// speedup vs baseline: 1.4747x; 1.0744x over previous
#include <cuda_runtime.h>
#include <cuda_fp16.h>
#include <cstdint>
#include <cstddef>

#define MM    3
#define NN    100000
#define DIN   128
#define DH    64
#define EDGES 1600000
#define NSEG  (MM * NN)
#define CAP   64                         // per-segment slot capacity (P(deg>64)~1e-20)

// ---------------- scratch (device globals; no allocations) ----------------
__device__ __half g_proj[(size_t)MM * NN * DH];  // 38.4 MB [m][n][h] fp16
__device__ __half g_hn  [(size_t)NN * MM * DH];  // 38.4 MB [n][m][h] fp16
__device__ int    g_count[NSEG];                 // per-(m,dst) degree
__device__ int    g_eidx[(size_t)NSEG * CAP];    // 76.8 MB binned src ids
__device__ float  g_logits[MM];

__device__ __forceinline__ float tanh_hw(float x) {
    float y;
    asm("tanh.approx.f32 %0, %1;" : "=f"(y) : "f"(x));
    return y;
}

// ---------------- K1: proj[m] = feats[m] @ W[m] — HMMA, 2D grid (y = m) ----
#define SAS 136                          // padded stride in halves (272 B)
__global__ __launch_bounds__(128) void k_proj(const float* __restrict__ feats,
                                              const float* __restrict__ W) {
    extern __shared__ __half dynh[];
    __half* sA  = dynh;                  // 128*136 halves = 34816 B
    __half* sWt = dynh + 128 * SAS;      // 64*136 halves  = 17408 B

    const int m = blockIdx.y;
    const int t = threadIdx.x;
    const int node0 = blockIdx.x * 128;
    const int lane = t & 31, w = t >> 5;
    const int gid = lane >> 2, tid4 = lane & 3;

    const float* fbase = feats + (size_t)m * NN * DIN;
    const float* wbase = W     + (size_t)m * DIN * DH;

    #pragma unroll
    for (int it = 0; it < 32; it++) {
        int idx = t + 128 * it;
        int row = idx >> 5;
        int c4  = idx & 31;
        int gn  = node0 + row;
        float4 v = make_float4(0.f, 0.f, 0.f, 0.f);
        if (gn < NN)
            v = *(const float4*)(fbase + (size_t)gn * DIN + c4 * 4);
        *(__half2*)&sA[row * SAS + c4 * 4]     = __floats2half2_rn(v.x, v.y);
        *(__half2*)&sA[row * SAS + c4 * 4 + 2] = __floats2half2_rn(v.z, v.w);
    }
    #pragma unroll
    for (int it = 0; it < 64; it++) {
        int idx = t + 128 * it;
        int k = idx >> 6;
        int n = idx & 63;
        sWt[n * SAS + k] = __float2half_rn(wbase[(size_t)k * DH + n]);
    }
    __syncthreads();

    float c[2][8][4];
    #pragma unroll
    for (int mt = 0; mt < 2; mt++)
        #pragma unroll
        for (int nt = 0; nt < 8; nt++)
            #pragma unroll
            for (int q = 0; q < 4; q++) c[mt][nt][q] = 0.f;

    #pragma unroll
    for (int ks = 0; ks < 8; ks++) {
        const int k0 = ks * 16;
        uint32_t a[2][4];
        #pragma unroll
        for (int mt = 0; mt < 2; mt++) {
            int r = w * 32 + mt * 16 + gid;
            a[mt][0] = *(const uint32_t*)&sA[r * SAS + k0 + tid4 * 2];
            a[mt][1] = *(const uint32_t*)&sA[(r + 8) * SAS + k0 + tid4 * 2];
            a[mt][2] = *(const uint32_t*)&sA[r * SAS + k0 + tid4 * 2 + 8];
            a[mt][3] = *(const uint32_t*)&sA[(r + 8) * SAS + k0 + tid4 * 2 + 8];
        }
        #pragma unroll
        for (int nt = 0; nt < 8; nt++) {
            int n = nt * 8 + gid;
            uint32_t b0 = *(const uint32_t*)&sWt[n * SAS + k0 + tid4 * 2];
            uint32_t b1 = *(const uint32_t*)&sWt[n * SAS + k0 + tid4 * 2 + 8];
            #pragma unroll
            for (int mt = 0; mt < 2; mt++) {
                asm volatile(
                    "mma.sync.aligned.m16n8k16.row.col.f32.f16.f16.f32 "
                    "{%0,%1,%2,%3}, {%4,%5,%6,%7}, {%8,%9}, {%0,%1,%2,%3};"
                    : "+f"(c[mt][nt][0]), "+f"(c[mt][nt][1]),
                      "+f"(c[mt][nt][2]), "+f"(c[mt][nt][3])
                    : "r"(a[mt][0]), "r"(a[mt][1]), "r"(a[mt][2]), "r"(a[mt][3]),
                      "r"(b0), "r"(b1));
            }
        }
    }

    __half* pbase = g_proj + (size_t)m * NN * DH;
    #pragma unroll
    for (int mt = 0; mt < 2; mt++) {
        int r0 = node0 + w * 32 + mt * 16 + gid;
        #pragma unroll
        for (int nt = 0; nt < 8; nt++) {
            int col = nt * 8 + tid4 * 2;
            if (r0 < NN)
                *(__half2*)(pbase + (size_t)r0 * DH + col) =
                    __floats2half2_rn(c[mt][nt][0], c[mt][nt][1]);
            if (r0 + 8 < NN)
                *(__half2*)(pbase + (size_t)(r0 + 8) * DH + col) =
                    __floats2half2_rn(c[mt][nt][2], c[mt][nt][3]);
        }
    }
}
#define PROJ_SMEM ((128 + 64) * SAS * 2)   // 52224 B

// ---------------- E1: single-pass capacity-binned edge sort ----------------
__global__ void k_binedges(const int* __restrict__ src, const int* __restrict__ dst,
                           int m) {
    int e = blockIdx.x * blockDim.x + threadIdx.x;
    if (e >= EDGES) return;
    int s = __ldg(src + (size_t)m * EDGES + e);
    int d = __ldg(dst + (size_t)m * EDGES + e);
    long seg = (long)m * NN + d;
    int r = atomicAdd(&g_count[seg], 1);
    if (r < CAP)
        g_eidx[(size_t)seg * CAP + r] = s;
}

// ---------------- E4: per-m gather-reduce + mean + bias + prelu ------------
// 8 lanes per segment; unroll-4 independent gather chains per thread.
__global__ void k_aggregate(const float* __restrict__ b,
                            const float* __restrict__ prelu_a, int m) {
    long gt   = (long)blockIdx.x * blockDim.x + threadIdx.x;
    long nl   = gt >> 3;                    // node within m
    int  lane = (int)(gt & 7);
    if (nl >= NN) return;
    long gid = (long)m * NN + nl;

    int cnt = g_count[gid];
    int nv  = cnt < CAP ? cnt : CAP;

    const int*   ei = g_eidx + (size_t)gid * CAP;
    const uint4* pb = (const uint4*)g_proj + (size_t)m * NN * 8;
    float acc[8] = {0.f,0.f,0.f,0.f,0.f,0.f,0.f,0.f};

    int j = 0;
    for (; j + 3 < nv; j += 4) {
        int s0 = __ldg(&ei[j]);
        int s1 = __ldg(&ei[j + 1]);
        int s2 = __ldg(&ei[j + 2]);
        int s3 = __ldg(&ei[j + 3]);
        uint4 v0 = __ldg(&pb[(size_t)s0 * 8 + lane]);
        uint4 v1 = __ldg(&pb[(size_t)s1 * 8 + lane]);
        uint4 v2 = __ldg(&pb[(size_t)s2 * 8 + lane]);
        uint4 v3 = __ldg(&pb[(size_t)s3 * 8 + lane]);
        float2 f;
        f = __half22float2(*(__half2*)&v0.x); acc[0]+=f.x; acc[1]+=f.y;
        f = __half22float2(*(__half2*)&v0.y); acc[2]+=f.x; acc[3]+=f.y;
        f = __half22float2(*(__half2*)&v0.z); acc[4]+=f.x; acc[5]+=f.y;
        f = __half22float2(*(__half2*)&v0.w); acc[6]+=f.x; acc[7]+=f.y;
        f = __half22float2(*(__half2*)&v1.x); acc[0]+=f.x; acc[1]+=f.y;
        f = __half22float2(*(__half2*)&v1.y); acc[2]+=f.x; acc[3]+=f.y;
        f = __half22float2(*(__half2*)&v1.z); acc[4]+=f.x; acc[5]+=f.y;
        f = __half22float2(*(__half2*)&v1.w); acc[6]+=f.x; acc[7]+=f.y;
        f = __half22float2(*(__half2*)&v2.x); acc[0]+=f.x; acc[1]+=f.y;
        f = __half22float2(*(__half2*)&v2.y); acc[2]+=f.x; acc[3]+=f.y;
        f = __half22float2(*(__half2*)&v2.z); acc[4]+=f.x; acc[5]+=f.y;
        f = __half22float2(*(__half2*)&v2.w); acc[6]+=f.x; acc[7]+=f.y;
        f = __half22float2(*(__half2*)&v3.x); acc[0]+=f.x; acc[1]+=f.y;
        f = __half22float2(*(__half2*)&v3.y); acc[2]+=f.x; acc[3]+=f.y;
        f = __half22float2(*(__half2*)&v3.z); acc[4]+=f.x; acc[5]+=f.y;
        f = __half22float2(*(__half2*)&v3.w); acc[6]+=f.x; acc[7]+=f.y;
    }
    for (; j < nv; j++) {
        int s0 = __ldg(&ei[j]);
        uint4 v0 = __ldg(&pb[(size_t)s0 * 8 + lane]);
        float2 f;
        f = __half22float2(*(__half2*)&v0.x); acc[0]+=f.x; acc[1]+=f.y;
        f = __half22float2(*(__half2*)&v0.y); acc[2]+=f.x; acc[3]+=f.y;
        f = __half22float2(*(__half2*)&v0.z); acc[4]+=f.x; acc[5]+=f.y;
        f = __half22float2(*(__half2*)&v0.w); acc[6]+=f.x; acc[7]+=f.y;
    }

    float inv   = 1.0f / fmaxf((float)cnt, 1.0f);
    float alpha = __ldg(prelu_a + m);
    const float* bp = b + m * DH + lane * 8;
    float h[8];
    #pragma unroll
    for (int c = 0; c < 8; c++) {
        float x = acc[c] * inv + __ldg(bp + c);
        h[c] = x > 0.f ? x : alpha * x;
    }
    union { __half2 p[4]; uint4 u; } pk;
    #pragma unroll
    for (int c = 0; c < 4; c++)
        pk.p[c] = __floats2half2_rn(h[2*c], h[2*c+1]);
    ((uint4*)(g_hn + ((size_t)nl * MM + m) * DH))[lane] = pk.u;
}

// ---------------- K4: per-m logits via HMMA -------------------------------
#define ASTR 72                          // 144-B padded row stride (halves)
__global__ __launch_bounds__(128) void k_attnlogits(const float* __restrict__ fc_W,
                                                    const float* __restrict__ fc_b,
                                                    const float* __restrict__ attn,
                                                    int m) {
    __shared__ __half sA [128 * ASTR];   // 18432 B
    __shared__ __half sWt[64 * ASTR];    //  9216 B
    __shared__ float sPart;

    const int t = threadIdx.x;
    const int node0 = blockIdx.x * 128;
    const int lane = t & 31, w = t >> 5;
    const int gid = lane >> 2, tid4 = lane & 3;

    if (t == 0) sPart = 0.f;

    #pragma unroll
    for (int it = 0; it < 8; it++) {
        int idx = t + 128 * it;
        int row = idx >> 3;
        int k8  = idx & 7;
        int n   = node0 + row;
        uint4 v = make_uint4(0u, 0u, 0u, 0u);
        if (n < NN)
            v = *((const uint4*)(g_hn + ((size_t)n * MM + m) * DH) + k8);
        *(uint4*)&sA[row * ASTR + k8 * 8] = v;
    }
    #pragma unroll
    for (int it = 0; it < 32; it++) {
        int idx = t + 128 * it;
        int k = idx >> 6;
        int n = idx & 63;
        sWt[n * ASTR + k] = __float2half_rn(fc_W[(size_t)k * DH + n]);
    }
    __syncthreads();

    float c[2][8][4];
    #pragma unroll
    for (int mt = 0; mt < 2; mt++)
        #pragma unroll
        for (int nt = 0; nt < 8; nt++)
            #pragma unroll
            for (int q = 0; q < 4; q++) c[mt][nt][q] = 0.f;

    #pragma unroll
    for (int ks = 0; ks < 4; ks++) {
        const int k0 = ks * 16;
        uint32_t a[2][4];
        #pragma unroll
        for (int mt = 0; mt < 2; mt++) {
            int r = w * 32 + mt * 16 + gid;
            a[mt][0] = *(const uint32_t*)&sA[r * ASTR + k0 + tid4 * 2];
            a[mt][1] = *(const uint32_t*)&sA[(r + 8) * ASTR + k0 + tid4 * 2];
            a[mt][2] = *(const uint32_t*)&sA[r * ASTR + k0 + tid4 * 2 + 8];
            a[mt][3] = *(const uint32_t*)&sA[(r + 8) * ASTR + k0 + tid4 * 2 + 8];
        }
        #pragma unroll
        for (int nt = 0; nt < 8; nt++) {
            int n = nt * 8 + gid;
            uint32_t b0 = *(const uint32_t*)&sWt[n * ASTR + k0 + tid4 * 2];
            uint32_t b1 = *(const uint32_t*)&sWt[n * ASTR + k0 + tid4 * 2 + 8];
            #pragma unroll
            for (int mt = 0; mt < 2; mt++) {
                asm volatile(
                    "mma.sync.aligned.m16n8k16.row.col.f32.f16.f16.f32 "
                    "{%0,%1,%2,%3}, {%4,%5,%6,%7}, {%8,%9}, {%0,%1,%2,%3};"
                    : "+f"(c[mt][nt][0]), "+f"(c[mt][nt][1]),
                      "+f"(c[mt][nt][2]), "+f"(c[mt][nt][3])
                    : "r"(a[mt][0]), "r"(a[mt][1]), "r"(a[mt][2]), "r"(a[mt][3]),
                      "r"(b0), "r"(b1));
            }
        }
    }

    float csum = 0.f;
    #pragma unroll
    for (int mt = 0; mt < 2; mt++) {
        int r0 = node0 + w * 32 + mt * 16 + gid;
        bool ok0 = r0 < NN, ok1 = (r0 + 8) < NN;
        #pragma unroll
        for (int nt = 0; nt < 8; nt++) {
            int col = nt * 8 + tid4 * 2;
            float a0 = __ldg(attn + col),   a1 = __ldg(attn + col + 1);
            float bb0 = __ldg(fc_b + col),  bb1 = __ldg(fc_b + col + 1);
            if (ok0)
                csum += tanh_hw(c[mt][nt][0] + bb0) * a0
                      + tanh_hw(c[mt][nt][1] + bb1) * a1;
            if (ok1)
                csum += tanh_hw(c[mt][nt][2] + bb0) * a0
                      + tanh_hw(c[mt][nt][3] + bb1) * a1;
        }
    }
    #pragma unroll
    for (int o = 16; o > 0; o >>= 1)
        csum += __shfl_xor_sync(0xffffffffu, csum, o);
    if (lane == 0) atomicAdd(&sPart, csum);
    __syncthreads();
    if (t == 0) atomicAdd(&g_logits[m], sPart * (1.0f / (float)NN));
}

// ---------------- K5: softmax(logits) + z = sum_m beta_m * hn[:,m,:] -------
__global__ void k_combine(float* __restrict__ out) {
    const long tid = (long)blockIdx.x * blockDim.x + threadIdx.x;
    if (tid >= (long)NN * 8) return;
    const int  q = (int)(tid & 7);
    const long n = tid >> 3;

    float l0 = g_logits[0], l1 = g_logits[1], l2 = g_logits[2];
    float mx = fmaxf(l0, fmaxf(l1, l2));
    float e0 = __expf(l0 - mx), e1 = __expf(l1 - mx), e2 = __expf(l2 - mx);
    float is = 1.0f / (e0 + e1 + e2);
    float b0 = e0 * is, b1 = e1 * is, b2 = e2 * is;

    const uint4* r = (const uint4*)(g_hn + (size_t)n * (MM * DH)) + q;
    uint4 u0 = __ldg(r), u1 = __ldg(r + 8), u2 = __ldg(r + 16);

    float o[8];
    #pragma unroll
    for (int c = 0; c < 4; c++) {
        float2 f0 = __half22float2(((const __half2*)&u0)[c]);
        float2 f1 = __half22float2(((const __half2*)&u1)[c]);
        float2 f2 = __half22float2(((const __half2*)&u2)[c]);
        o[2*c]   = b0 * f0.x + b1 * f1.x + b2 * f2.x;
        o[2*c+1] = b0 * f0.y + b1 * f1.y + b2 * f2.y;
    }
    float* op = out + (size_t)n * DH + q * 8;
    *(float4*)op       = make_float4(o[0], o[1], o[2], o[3]);
    *(float4*)(op + 4) = make_float4(o[4], o[5], o[6], o[7]);
}

// ---------------- launcher: 3 chain streams + default (proj 2D on s0) ------
static cudaStream_t sc[MM] = {nullptr, nullptr, nullptr};
static cudaEvent_t  evFork = nullptr, evPj = nullptr;
static cudaEvent_t  evAt[MM];

extern "C" void kernel_launch(void* const* d_in, const int* in_sizes, int n_in,
                              void* d_out, int out_size) {
    const float* feats   = (const float*)d_in[0];
    const int*   src     = (const int*)  d_in[1];
    const int*   dst     = (const int*)  d_in[2];
    const float* W       = (const float*)d_in[3];
    const float* b       = (const float*)d_in[4];
    const float* prelu_a = (const float*)d_in[5];
    const float* fc_W    = (const float*)d_in[6];
    const float* fc_b    = (const float*)d_in[7];
    const float* attn    = (const float*)d_in[8];
    float* out = (float*)d_out;

    if (!sc[0]) {
        for (int m = 0; m < MM; m++) {
            cudaStreamCreateWithFlags(&sc[m], cudaStreamNonBlocking);
            cudaEventCreateWithFlags(&evAt[m], cudaEventDisableTiming);
        }
        cudaEventCreateWithFlags(&evFork, cudaEventDisableTiming);
        cudaEventCreateWithFlags(&evPj,   cudaEventDisableTiming);
    }

    void *p_cnt, *p_log;
    cudaGetSymbolAddress(&p_cnt, g_count);
    cudaGetSymbolAddress(&p_log, g_logits);

    cudaFuncSetAttribute(k_proj,
                         cudaFuncAttributeMaxDynamicSharedMemorySize, PROJ_SMEM);

    const unsigned geb = (EDGES + 255) / 256;
    const unsigned gnb = (NN + 127) / 128;                // 782 blocks
    const unsigned gagg = (unsigned)(((long)NN * 8 + 255) / 256);
    const unsigned gab = (unsigned)(((long)NN * 8 + 255) / 256);

    // s0: clear count + logits, then fork
    cudaMemsetAsync(p_cnt, 0, sizeof(int) * NSEG, 0);
    cudaMemsetAsync(p_log, 0, sizeof(float) * MM, 0);
    cudaEventRecord(evFork, 0);

    // chains: binedges_m first (overlaps proj below)
    for (int m = 0; m < MM; m++) {
        cudaStreamWaitEvent(sc[m], evFork, 0);
        k_binedges<<<geb, 256, 0, sc[m]>>>(src, dst, m);
    }

    // s0: all-m projection in ONE 2D launch (full-chip concurrency)
    dim3 gproj(gnb, MM);
    k_proj<<<gproj, 128, PROJ_SMEM>>>(feats, W);
    cudaEventRecord(evPj, 0);

    // chains: aggregate_m (after binedges_m in-stream + proj event) -> attn_m
    for (int m = 0; m < MM; m++) {
        cudaStreamWaitEvent(sc[m], evPj, 0);
        k_aggregate<<<gagg, 256, 0, sc[m]>>>(b, prelu_a, m);
        k_attnlogits<<<gnb, 128, 0, sc[m]>>>(fc_W, fc_b, attn, m);
        cudaEventRecord(evAt[m], sc[m]);
    }

    // s0: combine after all chains
    for (int m = 0; m < MM; m++)
        cudaStreamWaitEvent(0, evAt[m], 0);
    k_combine<<<gab, 256>>>(out);
}

// round 15
// speedup vs baseline: 1.7169x; 1.1642x over previous
#include <cuda_runtime.h>
#include <cuda_fp16.h>
#include <cstdint>
#include <cstddef>

#define MM    3
#define NN    100000
#define DIN   128
#define DH    64
#define EDGES 1600000
#define NSEG  (MM * NN)
#define CAP   64                         // per-segment slot capacity (P(deg>64)~1e-20)

// ---------------- scratch (device globals; no allocations) ----------------
__device__ __half g_proj[(size_t)MM * NN * DH];  // 38.4 MB [m][n][h] fp16
__device__ __half g_hn  [(size_t)NN * MM * DH];  // 38.4 MB [n][m][h] fp16
__device__ int    g_count[NSEG];                 // per-(m,dst) degree
__device__ int    g_eidx[(size_t)NSEG * CAP];    // 76.8 MB binned src ids
__device__ float  g_logits[MM];

__device__ __forceinline__ float tanh_hw(float x) {
    float y;
    asm("tanh.approx.f32 %0, %1;" : "=f"(y) : "f"(x));
    return y;
}

// ---------------- K1: proj[m] = feats[m] @ W[m] — HMMA, 2D grid, k-chunked -
// sA holds one 64-wide K chunk (18.4 KB); sWt holds full K (17.4 KB).
// Total 35.8 KB -> 6 blocks/SM (was 4 at 52 KB).
#define ACH 72                           // sA row stride in halves (144 B)
#define WST 136                          // sWt row stride in halves (272 B)
__global__ __launch_bounds__(128) void k_proj(const float* __restrict__ feats,
                                              const float* __restrict__ W) {
    extern __shared__ __half dynh[];
    __half* sA  = dynh;                  // 128*72  = 18432 B
    __half* sWt = dynh + 128 * ACH;      // 64*136  = 17408 B

    const int m = blockIdx.y;
    const int t = threadIdx.x;
    const int node0 = blockIdx.x * 128;
    const int lane = t & 31, w = t >> 5;
    const int gid = lane >> 2, tid4 = lane & 3;

    const float* fbase = feats + (size_t)m * NN * DIN;
    const float* wbase = W     + (size_t)m * DIN * DH;

    // W 128x64 fp32 -> sWt[n][k] fp16 (transposed), once
    #pragma unroll
    for (int it = 0; it < 64; it++) {
        int idx = t + 128 * it;
        int k = idx >> 6;
        int n = idx & 63;
        sWt[n * WST + k] = __float2half_rn(wbase[(size_t)k * DH + n]);
    }

    float c[2][8][4];
    #pragma unroll
    for (int mt = 0; mt < 2; mt++)
        #pragma unroll
        for (int nt = 0; nt < 8; nt++)
            #pragma unroll
            for (int q = 0; q < 4; q++) c[mt][nt][q] = 0.f;

    #pragma unroll
    for (int kc = 0; kc < 2; kc++) {
        __syncthreads();
        // feats chunk: 128 rows x 64 k = 2048 float4 / 128 thr = 16 each
        #pragma unroll
        for (int it = 0; it < 16; it++) {
            int idx = t + 128 * it;
            int row = idx >> 4;
            int c4  = idx & 15;
            int gn  = node0 + row;
            float4 v = make_float4(0.f, 0.f, 0.f, 0.f);
            if (gn < NN)
                v = *(const float4*)(fbase + (size_t)gn * DIN + kc * 64 + c4 * 4);
            *(__half2*)&sA[row * ACH + c4 * 4]     = __floats2half2_rn(v.x, v.y);
            *(__half2*)&sA[row * ACH + c4 * 4 + 2] = __floats2half2_rn(v.z, v.w);
        }
        __syncthreads();

        #pragma unroll
        for (int ks = 0; ks < 4; ks++) {
            const int k0 = ks * 16;                 // within chunk
            const int kw = kc * 64 + k0;            // within full K (for sWt)
            uint32_t a[2][4];
            #pragma unroll
            for (int mt = 0; mt < 2; mt++) {
                int r = w * 32 + mt * 16 + gid;
                a[mt][0] = *(const uint32_t*)&sA[r * ACH + k0 + tid4 * 2];
                a[mt][1] = *(const uint32_t*)&sA[(r + 8) * ACH + k0 + tid4 * 2];
                a[mt][2] = *(const uint32_t*)&sA[r * ACH + k0 + tid4 * 2 + 8];
                a[mt][3] = *(const uint32_t*)&sA[(r + 8) * ACH + k0 + tid4 * 2 + 8];
            }
            #pragma unroll
            for (int nt = 0; nt < 8; nt++) {
                int n = nt * 8 + gid;
                uint32_t b0 = *(const uint32_t*)&sWt[n * WST + kw + tid4 * 2];
                uint32_t b1 = *(const uint32_t*)&sWt[n * WST + kw + tid4 * 2 + 8];
                #pragma unroll
                for (int mt = 0; mt < 2; mt++) {
                    asm volatile(
                        "mma.sync.aligned.m16n8k16.row.col.f32.f16.f16.f32 "
                        "{%0,%1,%2,%3}, {%4,%5,%6,%7}, {%8,%9}, {%0,%1,%2,%3};"
                        : "+f"(c[mt][nt][0]), "+f"(c[mt][nt][1]),
                          "+f"(c[mt][nt][2]), "+f"(c[mt][nt][3])
                        : "r"(a[mt][0]), "r"(a[mt][1]), "r"(a[mt][2]), "r"(a[mt][3]),
                          "r"(b0), "r"(b1));
                }
            }
        }
    }

    __half* pbase = g_proj + (size_t)m * NN * DH;
    #pragma unroll
    for (int mt = 0; mt < 2; mt++) {
        int r0 = node0 + w * 32 + mt * 16 + gid;
        #pragma unroll
        for (int nt = 0; nt < 8; nt++) {
            int col = nt * 8 + tid4 * 2;
            if (r0 < NN)
                *(__half2*)(pbase + (size_t)r0 * DH + col) =
                    __floats2half2_rn(c[mt][nt][0], c[mt][nt][1]);
            if (r0 + 8 < NN)
                *(__half2*)(pbase + (size_t)(r0 + 8) * DH + col) =
                    __floats2half2_rn(c[mt][nt][2], c[mt][nt][3]);
        }
    }
}
#define PROJ_SMEM (128 * ACH * 2 + 64 * WST * 2)   // 35840 B

// ---------------- E1: single-pass capacity-binned edge sort (2D, y=m) ------
__global__ void k_binedges(const int* __restrict__ src, const int* __restrict__ dst) {
    int e = blockIdx.x * blockDim.x + threadIdx.x;
    if (e >= EDGES) return;
    int m = blockIdx.y;
    int s = __ldg(src + (size_t)m * EDGES + e);
    int d = __ldg(dst + (size_t)m * EDGES + e);
    long seg = (long)m * NN + d;
    int r = atomicAdd(&g_count[seg], 1);
    if (r < CAP)
        g_eidx[(size_t)seg * CAP + r] = s;
}

// ---------------- E4: per-m gather-reduce + mean + bias + prelu ------------
// 8 lanes per segment; unroll-4 independent gather chains per thread.
__global__ void k_aggregate(const float* __restrict__ b,
                            const float* __restrict__ prelu_a, int m) {
    long gt   = (long)blockIdx.x * blockDim.x + threadIdx.x;
    long nl   = gt >> 3;                    // node within m
    int  lane = (int)(gt & 7);
    if (nl >= NN) return;
    long gid = (long)m * NN + nl;

    int cnt = g_count[gid];
    int nv  = cnt < CAP ? cnt : CAP;

    const int*   ei = g_eidx + (size_t)gid * CAP;
    const uint4* pb = (const uint4*)g_proj + (size_t)m * NN * 8;
    float acc[8] = {0.f,0.f,0.f,0.f,0.f,0.f,0.f,0.f};

    int j = 0;
    for (; j + 3 < nv; j += 4) {
        int s0 = __ldg(&ei[j]);
        int s1 = __ldg(&ei[j + 1]);
        int s2 = __ldg(&ei[j + 2]);
        int s3 = __ldg(&ei[j + 3]);
        uint4 v0 = __ldg(&pb[(size_t)s0 * 8 + lane]);
        uint4 v1 = __ldg(&pb[(size_t)s1 * 8 + lane]);
        uint4 v2 = __ldg(&pb[(size_t)s2 * 8 + lane]);
        uint4 v3 = __ldg(&pb[(size_t)s3 * 8 + lane]);
        float2 f;
        f = __half22float2(*(__half2*)&v0.x); acc[0]+=f.x; acc[1]+=f.y;
        f = __half22float2(*(__half2*)&v0.y); acc[2]+=f.x; acc[3]+=f.y;
        f = __half22float2(*(__half2*)&v0.z); acc[4]+=f.x; acc[5]+=f.y;
        f = __half22float2(*(__half2*)&v0.w); acc[6]+=f.x; acc[7]+=f.y;
        f = __half22float2(*(__half2*)&v1.x); acc[0]+=f.x; acc[1]+=f.y;
        f = __half22float2(*(__half2*)&v1.y); acc[2]+=f.x; acc[3]+=f.y;
        f = __half22float2(*(__half2*)&v1.z); acc[4]+=f.x; acc[5]+=f.y;
        f = __half22float2(*(__half2*)&v1.w); acc[6]+=f.x; acc[7]+=f.y;
        f = __half22float2(*(__half2*)&v2.x); acc[0]+=f.x; acc[1]+=f.y;
        f = __half22float2(*(__half2*)&v2.y); acc[2]+=f.x; acc[3]+=f.y;
        f = __half22float2(*(__half2*)&v2.z); acc[4]+=f.x; acc[5]+=f.y;
        f = __half22float2(*(__half2*)&v2.w); acc[6]+=f.x; acc[7]+=f.y;
        f = __half22float2(*(__half2*)&v3.x); acc[0]+=f.x; acc[1]+=f.y;
        f = __half22float2(*(__half2*)&v3.y); acc[2]+=f.x; acc[3]+=f.y;
        f = __half22float2(*(__half2*)&v3.z); acc[4]+=f.x; acc[5]+=f.y;
        f = __half22float2(*(__half2*)&v3.w); acc[6]+=f.x; acc[7]+=f.y;
    }
    for (; j < nv; j++) {
        int s0 = __ldg(&ei[j]);
        uint4 v0 = __ldg(&pb[(size_t)s0 * 8 + lane]);
        float2 f;
        f = __half22float2(*(__half2*)&v0.x); acc[0]+=f.x; acc[1]+=f.y;
        f = __half22float2(*(__half2*)&v0.y); acc[2]+=f.x; acc[3]+=f.y;
        f = __half22float2(*(__half2*)&v0.z); acc[4]+=f.x; acc[5]+=f.y;
        f = __half22float2(*(__half2*)&v0.w); acc[6]+=f.x; acc[7]+=f.y;
    }

    float inv   = 1.0f / fmaxf((float)cnt, 1.0f);
    float alpha = __ldg(prelu_a + m);
    const float* bp = b + m * DH + lane * 8;
    float h[8];
    #pragma unroll
    for (int c = 0; c < 8; c++) {
        float x = acc[c] * inv + __ldg(bp + c);
        h[c] = x > 0.f ? x : alpha * x;
    }
    union { __half2 p[4]; uint4 u; } pk;
    #pragma unroll
    for (int c = 0; c < 4; c++)
        pk.p[c] = __floats2half2_rn(h[2*c], h[2*c+1]);
    ((uint4*)(g_hn + ((size_t)nl * MM + m) * DH))[lane] = pk.u;
}

// ---------------- K4: logits via HMMA (2D, y=m) ----------------------------
#define ASTR 72                          // 144-B padded row stride (halves)
__global__ __launch_bounds__(128) void k_attnlogits(const float* __restrict__ fc_W,
                                                    const float* __restrict__ fc_b,
                                                    const float* __restrict__ attn) {
    __shared__ __half sA [128 * ASTR];   // 18432 B
    __shared__ __half sWt[64 * ASTR];    //  9216 B
    __shared__ float sPart;

    const int m = blockIdx.y;
    const int t = threadIdx.x;
    const int node0 = blockIdx.x * 128;
    const int lane = t & 31, w = t >> 5;
    const int gid = lane >> 2, tid4 = lane & 3;

    if (t == 0) sPart = 0.f;

    #pragma unroll
    for (int it = 0; it < 8; it++) {
        int idx = t + 128 * it;
        int row = idx >> 3;
        int k8  = idx & 7;
        int n   = node0 + row;
        uint4 v = make_uint4(0u, 0u, 0u, 0u);
        if (n < NN)
            v = *((const uint4*)(g_hn + ((size_t)n * MM + m) * DH) + k8);
        *(uint4*)&sA[row * ASTR + k8 * 8] = v;
    }
    #pragma unroll
    for (int it = 0; it < 32; it++) {
        int idx = t + 128 * it;
        int k = idx >> 6;
        int n = idx & 63;
        sWt[n * ASTR + k] = __float2half_rn(fc_W[(size_t)k * DH + n]);
    }
    __syncthreads();

    float c[2][8][4];
    #pragma unroll
    for (int mt = 0; mt < 2; mt++)
        #pragma unroll
        for (int nt = 0; nt < 8; nt++)
            #pragma unroll
            for (int q = 0; q < 4; q++) c[mt][nt][q] = 0.f;

    #pragma unroll
    for (int ks = 0; ks < 4; ks++) {
        const int k0 = ks * 16;
        uint32_t a[2][4];
        #pragma unroll
        for (int mt = 0; mt < 2; mt++) {
            int r = w * 32 + mt * 16 + gid;
            a[mt][0] = *(const uint32_t*)&sA[r * ASTR + k0 + tid4 * 2];
            a[mt][1] = *(const uint32_t*)&sA[(r + 8) * ASTR + k0 + tid4 * 2];
            a[mt][2] = *(const uint32_t*)&sA[r * ASTR + k0 + tid4 * 2 + 8];
            a[mt][3] = *(const uint32_t*)&sA[(r + 8) * ASTR + k0 + tid4 * 2 + 8];
        }
        #pragma unroll
        for (int nt = 0; nt < 8; nt++) {
            int n = nt * 8 + gid;
            uint32_t b0 = *(const uint32_t*)&sWt[n * ASTR + k0 + tid4 * 2];
            uint32_t b1 = *(const uint32_t*)&sWt[n * ASTR + k0 + tid4 * 2 + 8];
            #pragma unroll
            for (int mt = 0; mt < 2; mt++) {
                asm volatile(
                    "mma.sync.aligned.m16n8k16.row.col.f32.f16.f16.f32 "
                    "{%0,%1,%2,%3}, {%4,%5,%6,%7}, {%8,%9}, {%0,%1,%2,%3};"
                    : "+f"(c[mt][nt][0]), "+f"(c[mt][nt][1]),
                      "+f"(c[mt][nt][2]), "+f"(c[mt][nt][3])
                    : "r"(a[mt][0]), "r"(a[mt][1]), "r"(a[mt][2]), "r"(a[mt][3]),
                      "r"(b0), "r"(b1));
            }
        }
    }

    float csum = 0.f;
    #pragma unroll
    for (int mt = 0; mt < 2; mt++) {
        int r0 = node0 + w * 32 + mt * 16 + gid;
        bool ok0 = r0 < NN, ok1 = (r0 + 8) < NN;
        #pragma unroll
        for (int nt = 0; nt < 8; nt++) {
            int col = nt * 8 + tid4 * 2;
            float a0 = __ldg(attn + col),   a1 = __ldg(attn + col + 1);
            float bb0 = __ldg(fc_b + col),  bb1 = __ldg(fc_b + col + 1);
            if (ok0)
                csum += tanh_hw(c[mt][nt][0] + bb0) * a0
                      + tanh_hw(c[mt][nt][1] + bb1) * a1;
            if (ok1)
                csum += tanh_hw(c[mt][nt][2] + bb0) * a0
                      + tanh_hw(c[mt][nt][3] + bb1) * a1;
        }
    }
    #pragma unroll
    for (int o = 16; o > 0; o >>= 1)
        csum += __shfl_xor_sync(0xffffffffu, csum, o);
    if (lane == 0) atomicAdd(&sPart, csum);
    __syncthreads();
    if (t == 0) atomicAdd(&g_logits[m], sPart * (1.0f / (float)NN));
}

// ---------------- K5: softmax(logits) + z = sum_m beta_m * hn[:,m,:] -------
__global__ void k_combine(float* __restrict__ out) {
    const long tid = (long)blockIdx.x * blockDim.x + threadIdx.x;
    if (tid >= (long)NN * 8) return;
    const int  q = (int)(tid & 7);
    const long n = tid >> 3;

    float l0 = g_logits[0], l1 = g_logits[1], l2 = g_logits[2];
    float mx = fmaxf(l0, fmaxf(l1, l2));
    float e0 = __expf(l0 - mx), e1 = __expf(l1 - mx), e2 = __expf(l2 - mx);
    float is = 1.0f / (e0 + e1 + e2);
    float b0 = e0 * is, b1 = e1 * is, b2 = e2 * is;

    const uint4* r = (const uint4*)(g_hn + (size_t)n * (MM * DH)) + q;
    uint4 u0 = __ldg(r), u1 = __ldg(r + 8), u2 = __ldg(r + 16);

    float o[8];
    #pragma unroll
    for (int c = 0; c < 4; c++) {
        float2 f0 = __half22float2(((const __half2*)&u0)[c]);
        float2 f1 = __half22float2(((const __half2*)&u1)[c]);
        float2 f2 = __half22float2(((const __half2*)&u2)[c]);
        o[2*c]   = b0 * f0.x + b1 * f1.x + b2 * f2.x;
        o[2*c+1] = b0 * f0.y + b1 * f1.y + b2 * f2.y;
    }
    float* op = out + (size_t)n * DH + q * 8;
    *(float4*)op       = make_float4(o[0], o[1], o[2], o[3]);
    *(float4*)(op + 4) = make_float4(o[4], o[5], o[6], o[7]);
}

// ---------------- launcher ----------------
static cudaStream_t sc[MM] = {nullptr, nullptr, nullptr};
static cudaEvent_t  evFork = nullptr, evPj = nullptr, evBin = nullptr;
static cudaEvent_t  evAg[MM];

extern "C" void kernel_launch(void* const* d_in, const int* in_sizes, int n_in,
                              void* d_out, int out_size) {
    const float* feats   = (const float*)d_in[0];
    const int*   src     = (const int*)  d_in[1];
    const int*   dst     = (const int*)  d_in[2];
    const float* W       = (const float*)d_in[3];
    const float* b       = (const float*)d_in[4];
    const float* prelu_a = (const float*)d_in[5];
    const float* fc_W    = (const float*)d_in[6];
    const float* fc_b    = (const float*)d_in[7];
    const float* attn    = (const float*)d_in[8];
    float* out = (float*)d_out;

    if (!sc[0]) {
        for (int m = 0; m < MM; m++) {
            cudaStreamCreateWithFlags(&sc[m], cudaStreamNonBlocking);
            cudaEventCreateWithFlags(&evAg[m], cudaEventDisableTiming);
        }
        cudaEventCreateWithFlags(&evFork, cudaEventDisableTiming);
        cudaEventCreateWithFlags(&evPj,   cudaEventDisableTiming);
        cudaEventCreateWithFlags(&evBin,  cudaEventDisableTiming);
    }

    void *p_cnt, *p_log;
    cudaGetSymbolAddress(&p_cnt, g_count);
    cudaGetSymbolAddress(&p_log, g_logits);

    cudaFuncSetAttribute(k_proj,
                         cudaFuncAttributeMaxDynamicSharedMemorySize, PROJ_SMEM);

    const unsigned geb = (EDGES + 255) / 256;
    const unsigned gnb = (NN + 127) / 128;                // 782 blocks
    const unsigned gagg = (unsigned)(((long)NN * 8 + 255) / 256);
    const unsigned gab = (unsigned)(((long)NN * 8 + 255) / 256);

    // s0: clear count + logits, then fork
    cudaMemsetAsync(p_cnt, 0, sizeof(int) * NSEG, 0);
    cudaMemsetAsync(p_log, 0, sizeof(float) * MM, 0);
    cudaEventRecord(evFork, 0);

    // sc0: all-m edge binning (one 2D launch), overlaps proj
    cudaStreamWaitEvent(sc[0], evFork, 0);
    dim3 gbin(geb, MM);
    k_binedges<<<gbin, 256, 0, sc[0]>>>(src, dst);
    cudaEventRecord(evBin, sc[0]);

    // s0: all-m projection (one 2D launch)
    dim3 gproj(gnb, MM);
    k_proj<<<gproj, 128, PROJ_SMEM>>>(feats, W);
    cudaEventRecord(evPj, 0);

    // per-m aggregate on the 3 streams (launch order puts agg1 at ncu's -s 5)
    for (int m = 0; m < MM; m++) {
        cudaStreamWaitEvent(sc[m], evBin, 0);
        cudaStreamWaitEvent(sc[m], evPj, 0);
        k_aggregate<<<gagg, 256, 0, sc[m]>>>(b, prelu_a, m);
        cudaEventRecord(evAg[m], sc[m]);
    }

    // s0: all-m attn logits (one 2D launch) after all aggs
    for (int m = 0; m < MM; m++)
        cudaStreamWaitEvent(0, evAg[m], 0);
    dim3 gattn(gnb, MM);
    k_attnlogits<<<gattn, 128>>>(fc_W, fc_b, attn);

    // s0: combine
    k_combine<<<gab, 256>>>(out);
}

// round 16
// speedup vs baseline: 1.7624x; 1.0265x over previous
#include <cuda_runtime.h>
#include <cuda_fp16.h>
#include <cstdint>
#include <cstddef>

#define MM    3
#define NN    100000
#define DIN   128
#define DH    64
#define EDGES 1600000
#define NSEG  (MM * NN)
#define CAP   64                         // per-segment slot capacity (P(deg>64)~1e-20)

// ---------------- scratch (device globals; no allocations) ----------------
__device__ __half g_proj[(size_t)MM * NN * DH];  // 38.4 MB [m][n][h] fp16
__device__ __half g_hn  [(size_t)NN * MM * DH];  // 38.4 MB [n][m][h] fp16
__device__ int    g_count[NSEG];                 // per-(m,dst) degree
__device__ int    g_eidx[(size_t)NSEG * CAP];    // 76.8 MB binned src ids
__device__ float  g_logits[MM];

__device__ __forceinline__ float tanh_hw(float x) {
    float y;
    asm("tanh.approx.f32 %0, %1;" : "=f"(y) : "f"(x));
    return y;
}

// ---------------- K1: proj[m] = feats[m] @ W[m] — HMMA, 2D grid, k-chunked -
#define ACH 72                           // sA row stride in halves (144 B)
#define WST 136                          // sWt row stride in halves (272 B)
__global__ __launch_bounds__(128) void k_proj(const float* __restrict__ feats,
                                              const float* __restrict__ W) {
    extern __shared__ __half dynh[];
    __half* sA  = dynh;                  // 128*72  = 18432 B
    __half* sWt = dynh + 128 * ACH;      // 64*136  = 17408 B

    const int m = blockIdx.y;
    const int t = threadIdx.x;
    const int node0 = blockIdx.x * 128;
    const int lane = t & 31, w = t >> 5;
    const int gid = lane >> 2, tid4 = lane & 3;

    const float* fbase = feats + (size_t)m * NN * DIN;
    const float* wbase = W     + (size_t)m * DIN * DH;

    #pragma unroll
    for (int it = 0; it < 64; it++) {
        int idx = t + 128 * it;
        int k = idx >> 6;
        int n = idx & 63;
        sWt[n * WST + k] = __float2half_rn(wbase[(size_t)k * DH + n]);
    }

    float c[2][8][4];
    #pragma unroll
    for (int mt = 0; mt < 2; mt++)
        #pragma unroll
        for (int nt = 0; nt < 8; nt++)
            #pragma unroll
            for (int q = 0; q < 4; q++) c[mt][nt][q] = 0.f;

    #pragma unroll
    for (int kc = 0; kc < 2; kc++) {
        __syncthreads();
        #pragma unroll
        for (int it = 0; it < 16; it++) {
            int idx = t + 128 * it;
            int row = idx >> 4;
            int c4  = idx & 15;
            int gn  = node0 + row;
            float4 v = make_float4(0.f, 0.f, 0.f, 0.f);
            if (gn < NN)
                v = *(const float4*)(fbase + (size_t)gn * DIN + kc * 64 + c4 * 4);
            *(__half2*)&sA[row * ACH + c4 * 4]     = __floats2half2_rn(v.x, v.y);
            *(__half2*)&sA[row * ACH + c4 * 4 + 2] = __floats2half2_rn(v.z, v.w);
        }
        __syncthreads();

        #pragma unroll
        for (int ks = 0; ks < 4; ks++) {
            const int k0 = ks * 16;
            const int kw = kc * 64 + k0;
            uint32_t a[2][4];
            #pragma unroll
            for (int mt = 0; mt < 2; mt++) {
                int r = w * 32 + mt * 16 + gid;
                a[mt][0] = *(const uint32_t*)&sA[r * ACH + k0 + tid4 * 2];
                a[mt][1] = *(const uint32_t*)&sA[(r + 8) * ACH + k0 + tid4 * 2];
                a[mt][2] = *(const uint32_t*)&sA[r * ACH + k0 + tid4 * 2 + 8];
                a[mt][3] = *(const uint32_t*)&sA[(r + 8) * ACH + k0 + tid4 * 2 + 8];
            }
            #pragma unroll
            for (int nt = 0; nt < 8; nt++) {
                int n = nt * 8 + gid;
                uint32_t b0 = *(const uint32_t*)&sWt[n * WST + kw + tid4 * 2];
                uint32_t b1 = *(const uint32_t*)&sWt[n * WST + kw + tid4 * 2 + 8];
                #pragma unroll
                for (int mt = 0; mt < 2; mt++) {
                    asm volatile(
                        "mma.sync.aligned.m16n8k16.row.col.f32.f16.f16.f32 "
                        "{%0,%1,%2,%3}, {%4,%5,%6,%7}, {%8,%9}, {%0,%1,%2,%3};"
                        : "+f"(c[mt][nt][0]), "+f"(c[mt][nt][1]),
                          "+f"(c[mt][nt][2]), "+f"(c[mt][nt][3])
                        : "r"(a[mt][0]), "r"(a[mt][1]), "r"(a[mt][2]), "r"(a[mt][3]),
                          "r"(b0), "r"(b1));
                }
            }
        }
    }

    __half* pbase = g_proj + (size_t)m * NN * DH;
    #pragma unroll
    for (int mt = 0; mt < 2; mt++) {
        int r0 = node0 + w * 32 + mt * 16 + gid;
        #pragma unroll
        for (int nt = 0; nt < 8; nt++) {
            int col = nt * 8 + tid4 * 2;
            if (r0 < NN)
                *(__half2*)(pbase + (size_t)r0 * DH + col) =
                    __floats2half2_rn(c[mt][nt][0], c[mt][nt][1]);
            if (r0 + 8 < NN)
                *(__half2*)(pbase + (size_t)(r0 + 8) * DH + col) =
                    __floats2half2_rn(c[mt][nt][2], c[mt][nt][3]);
        }
    }
}
#define PROJ_SMEM (128 * ACH * 2 + 64 * WST * 2)   // 35840 B

// ---------------- E1: single-pass capacity-binned edge sort (2D, y=m) ------
__global__ void k_binedges(const int* __restrict__ src, const int* __restrict__ dst) {
    int e = blockIdx.x * blockDim.x + threadIdx.x;
    if (e >= EDGES) return;
    int m = blockIdx.y;
    int s = __ldg(src + (size_t)m * EDGES + e);
    int d = __ldg(dst + (size_t)m * EDGES + e);
    long seg = (long)m * NN + d;
    int r = atomicAdd(&g_count[seg], 1);
    if (r < CAP)
        g_eidx[(size_t)seg * CAP + r] = s;
}

// ---------------- E4: gather-reduce — int4 eidx loads + pairwise HADD2 -----
__global__ void k_aggregate(const float* __restrict__ b,
                            const float* __restrict__ prelu_a, int m) {
    long gt   = (long)blockIdx.x * blockDim.x + threadIdx.x;
    long nl   = gt >> 3;                    // node within m
    int  lane = (int)(gt & 7);
    if (nl >= NN) return;
    long gid = (long)m * NN + nl;

    int cnt = g_count[gid];
    int nv  = cnt < CAP ? cnt : CAP;

    const int*   ei = g_eidx + (size_t)gid * CAP;   // 256-B aligned base
    const uint4* pb = (const uint4*)g_proj + (size_t)m * NN * 8;
    float acc[8] = {0.f,0.f,0.f,0.f,0.f,0.f,0.f,0.f};

    int j = 0;
    for (; j + 3 < nv; j += 4) {
        int4 ss = __ldg((const int4*)&ei[j]);       // 16-B aligned (j%4==0)
        uint4 v0 = __ldg(&pb[(size_t)ss.x * 8 + lane]);
        uint4 v1 = __ldg(&pb[(size_t)ss.y * 8 + lane]);
        uint4 v2 = __ldg(&pb[(size_t)ss.z * 8 + lane]);
        uint4 v3 = __ldg(&pb[(size_t)ss.w * 8 + lane]);
        // pairwise fp16 adds, then convert pair-sums to fp32
        __half2 p; float2 f;
        p = __hadd2(*(__half2*)&v0.x, *(__half2*)&v1.x);
        f = __half22float2(p); acc[0]+=f.x; acc[1]+=f.y;
        p = __hadd2(*(__half2*)&v0.y, *(__half2*)&v1.y);
        f = __half22float2(p); acc[2]+=f.x; acc[3]+=f.y;
        p = __hadd2(*(__half2*)&v0.z, *(__half2*)&v1.z);
        f = __half22float2(p); acc[4]+=f.x; acc[5]+=f.y;
        p = __hadd2(*(__half2*)&v0.w, *(__half2*)&v1.w);
        f = __half22float2(p); acc[6]+=f.x; acc[7]+=f.y;
        p = __hadd2(*(__half2*)&v2.x, *(__half2*)&v3.x);
        f = __half22float2(p); acc[0]+=f.x; acc[1]+=f.y;
        p = __hadd2(*(__half2*)&v2.y, *(__half2*)&v3.y);
        f = __half22float2(p); acc[2]+=f.x; acc[3]+=f.y;
        p = __hadd2(*(__half2*)&v2.z, *(__half2*)&v3.z);
        f = __half22float2(p); acc[4]+=f.x; acc[5]+=f.y;
        p = __hadd2(*(__half2*)&v2.w, *(__half2*)&v3.w);
        f = __half22float2(p); acc[6]+=f.x; acc[7]+=f.y;
    }
    for (; j < nv; j++) {
        int s0 = __ldg(&ei[j]);
        uint4 v0 = __ldg(&pb[(size_t)s0 * 8 + lane]);
        float2 f;
        f = __half22float2(*(__half2*)&v0.x); acc[0]+=f.x; acc[1]+=f.y;
        f = __half22float2(*(__half2*)&v0.y); acc[2]+=f.x; acc[3]+=f.y;
        f = __half22float2(*(__half2*)&v0.z); acc[4]+=f.x; acc[5]+=f.y;
        f = __half22float2(*(__half2*)&v0.w); acc[6]+=f.x; acc[7]+=f.y;
    }

    float inv   = 1.0f / fmaxf((float)cnt, 1.0f);
    float alpha = __ldg(prelu_a + m);
    const float* bp = b + m * DH + lane * 8;
    float h[8];
    #pragma unroll
    for (int c = 0; c < 8; c++) {
        float x = acc[c] * inv + __ldg(bp + c);
        h[c] = x > 0.f ? x : alpha * x;
    }
    union { __half2 p[4]; uint4 u; } pk;
    #pragma unroll
    for (int c = 0; c < 4; c++)
        pk.p[c] = __floats2half2_rn(h[2*c], h[2*c+1]);
    ((uint4*)(g_hn + ((size_t)nl * MM + m) * DH))[lane] = pk.u;
}

// ---------------- K4: logits via HMMA (2D, y=m) ----------------------------
#define ASTR 72                          // 144-B padded row stride (halves)
__global__ __launch_bounds__(128) void k_attnlogits(const float* __restrict__ fc_W,
                                                    const float* __restrict__ fc_b,
                                                    const float* __restrict__ attn) {
    __shared__ __half sA [128 * ASTR];   // 18432 B
    __shared__ __half sWt[64 * ASTR];    //  9216 B
    __shared__ float sPart;

    const int m = blockIdx.y;
    const int t = threadIdx.x;
    const int node0 = blockIdx.x * 128;
    const int lane = t & 31, w = t >> 5;
    const int gid = lane >> 2, tid4 = lane & 3;

    if (t == 0) sPart = 0.f;

    #pragma unroll
    for (int it = 0; it < 8; it++) {
        int idx = t + 128 * it;
        int row = idx >> 3;
        int k8  = idx & 7;
        int n   = node0 + row;
        uint4 v = make_uint4(0u, 0u, 0u, 0u);
        if (n < NN)
            v = *((const uint4*)(g_hn + ((size_t)n * MM + m) * DH) + k8);
        *(uint4*)&sA[row * ASTR + k8 * 8] = v;
    }
    #pragma unroll
    for (int it = 0; it < 32; it++) {
        int idx = t + 128 * it;
        int k = idx >> 6;
        int n = idx & 63;
        sWt[n * ASTR + k] = __float2half_rn(fc_W[(size_t)k * DH + n]);
    }
    __syncthreads();

    float c[2][8][4];
    #pragma unroll
    for (int mt = 0; mt < 2; mt++)
        #pragma unroll
        for (int nt = 0; nt < 8; nt++)
            #pragma unroll
            for (int q = 0; q < 4; q++) c[mt][nt][q] = 0.f;

    #pragma unroll
    for (int ks = 0; ks < 4; ks++) {
        const int k0 = ks * 16;
        uint32_t a[2][4];
        #pragma unroll
        for (int mt = 0; mt < 2; mt++) {
            int r = w * 32 + mt * 16 + gid;
            a[mt][0] = *(const uint32_t*)&sA[r * ASTR + k0 + tid4 * 2];
            a[mt][1] = *(const uint32_t*)&sA[(r + 8) * ASTR + k0 + tid4 * 2];
            a[mt][2] = *(const uint32_t*)&sA[r * ASTR + k0 + tid4 * 2 + 8];
            a[mt][3] = *(const uint32_t*)&sA[(r + 8) * ASTR + k0 + tid4 * 2 + 8];
        }
        #pragma unroll
        for (int nt = 0; nt < 8; nt++) {
            int n = nt * 8 + gid;
            uint32_t b0 = *(const uint32_t*)&sWt[n * ASTR + k0 + tid4 * 2];
            uint32_t b1 = *(const uint32_t*)&sWt[n * ASTR + k0 + tid4 * 2 + 8];
            #pragma unroll
            for (int mt = 0; mt < 2; mt++) {
                asm volatile(
                    "mma.sync.aligned.m16n8k16.row.col.f32.f16.f16.f32 "
                    "{%0,%1,%2,%3}, {%4,%5,%6,%7}, {%8,%9}, {%0,%1,%2,%3};"
                    : "+f"(c[mt][nt][0]), "+f"(c[mt][nt][1]),
                      "+f"(c[mt][nt][2]), "+f"(c[mt][nt][3])
                    : "r"(a[mt][0]), "r"(a[mt][1]), "r"(a[mt][2]), "r"(a[mt][3]),
                      "r"(b0), "r"(b1));
            }
        }
    }

    float csum = 0.f;
    #pragma unroll
    for (int mt = 0; mt < 2; mt++) {
        int r0 = node0 + w * 32 + mt * 16 + gid;
        bool ok0 = r0 < NN, ok1 = (r0 + 8) < NN;
        #pragma unroll
        for (int nt = 0; nt < 8; nt++) {
            int col = nt * 8 + tid4 * 2;
            float a0 = __ldg(attn + col),   a1 = __ldg(attn + col + 1);
            float bb0 = __ldg(fc_b + col),  bb1 = __ldg(fc_b + col + 1);
            if (ok0)
                csum += tanh_hw(c[mt][nt][0] + bb0) * a0
                      + tanh_hw(c[mt][nt][1] + bb1) * a1;
            if (ok1)
                csum += tanh_hw(c[mt][nt][2] + bb0) * a0
                      + tanh_hw(c[mt][nt][3] + bb1) * a1;
        }
    }
    #pragma unroll
    for (int o = 16; o > 0; o >>= 1)
        csum += __shfl_xor_sync(0xffffffffu, csum, o);
    if (lane == 0) atomicAdd(&sPart, csum);
    __syncthreads();
    if (t == 0) atomicAdd(&g_logits[m], sPart * (1.0f / (float)NN));
}

// ---------------- K5: softmax(logits) + z = sum_m beta_m * hn[:,m,:] -------
__global__ void k_combine(float* __restrict__ out) {
    const long tid = (long)blockIdx.x * blockDim.x + threadIdx.x;
    if (tid >= (long)NN * 8) return;
    const int  q = (int)(tid & 7);
    const long n = tid >> 3;

    float l0 = g_logits[0], l1 = g_logits[1], l2 = g_logits[2];
    float mx = fmaxf(l0, fmaxf(l1, l2));
    float e0 = __expf(l0 - mx), e1 = __expf(l1 - mx), e2 = __expf(l2 - mx);
    float is = 1.0f / (e0 + e1 + e2);
    float b0 = e0 * is, b1 = e1 * is, b2 = e2 * is;

    const uint4* r = (const uint4*)(g_hn + (size_t)n * (MM * DH)) + q;
    uint4 u0 = __ldg(r), u1 = __ldg(r + 8), u2 = __ldg(r + 16);

    float o[8];
    #pragma unroll
    for (int c = 0; c < 4; c++) {
        float2 f0 = __half22float2(((const __half2*)&u0)[c]);
        float2 f1 = __half22float2(((const __half2*)&u1)[c]);
        float2 f2 = __half22float2(((const __half2*)&u2)[c]);
        o[2*c]   = b0 * f0.x + b1 * f1.x + b2 * f2.x;
        o[2*c+1] = b0 * f0.y + b1 * f1.y + b2 * f2.y;
    }
    float* op = out + (size_t)n * DH + q * 8;
    *(float4*)op       = make_float4(o[0], o[1], o[2], o[3]);
    *(float4*)(op + 4) = make_float4(o[4], o[5], o[6], o[7]);
}

// ---------------- launcher ----------------
static cudaStream_t sc[MM] = {nullptr, nullptr, nullptr};
static cudaEvent_t  evFork = nullptr, evPj = nullptr, evBin = nullptr;
static cudaEvent_t  evAg[MM];

extern "C" void kernel_launch(void* const* d_in, const int* in_sizes, int n_in,
                              void* d_out, int out_size) {
    const float* feats   = (const float*)d_in[0];
    const int*   src     = (const int*)  d_in[1];
    const int*   dst     = (const int*)  d_in[2];
    const float* W       = (const float*)d_in[3];
    const float* b       = (const float*)d_in[4];
    const float* prelu_a = (const float*)d_in[5];
    const float* fc_W    = (const float*)d_in[6];
    const float* fc_b    = (const float*)d_in[7];
    const float* attn    = (const float*)d_in[8];
    float* out = (float*)d_out;

    if (!sc[0]) {
        for (int m = 0; m < MM; m++) {
            cudaStreamCreateWithFlags(&sc[m], cudaStreamNonBlocking);
            cudaEventCreateWithFlags(&evAg[m], cudaEventDisableTiming);
        }
        cudaEventCreateWithFlags(&evFork, cudaEventDisableTiming);
        cudaEventCreateWithFlags(&evPj,   cudaEventDisableTiming);
        cudaEventCreateWithFlags(&evBin,  cudaEventDisableTiming);
    }

    void *p_cnt, *p_log;
    cudaGetSymbolAddress(&p_cnt, g_count);
    cudaGetSymbolAddress(&p_log, g_logits);

    cudaFuncSetAttribute(k_proj,
                         cudaFuncAttributeMaxDynamicSharedMemorySize, PROJ_SMEM);

    const unsigned geb = (EDGES + 255) / 256;
    const unsigned gnb = (NN + 127) / 128;                // 782 blocks
    const unsigned gagg = (unsigned)(((long)NN * 8 + 255) / 256);
    const unsigned gab = (unsigned)(((long)NN * 8 + 255) / 256);

    // s0: clear count + logits, then fork
    cudaMemsetAsync(p_cnt, 0, sizeof(int) * NSEG, 0);
    cudaMemsetAsync(p_log, 0, sizeof(float) * MM, 0);
    cudaEventRecord(evFork, 0);

    // sc0: all-m edge binning (one 2D launch), overlaps proj
    cudaStreamWaitEvent(sc[0], evFork, 0);
    dim3 gbin(geb, MM);
    k_binedges<<<gbin, 256, 0, sc[0]>>>(src, dst);
    cudaEventRecord(evBin, sc[0]);

    // s0: all-m projection (one 2D launch)
    dim3 gproj(gnb, MM);
    k_proj<<<gproj, 128, PROJ_SMEM>>>(feats, W);
    cudaEventRecord(evPj, 0);

    // per-m aggregate on the 3 streams
    for (int m = 0; m < MM; m++) {
        cudaStreamWaitEvent(sc[m], evBin, 0);
        cudaStreamWaitEvent(sc[m], evPj, 0);
        k_aggregate<<<gagg, 256, 0, sc[m]>>>(b, prelu_a, m);
        cudaEventRecord(evAg[m], sc[m]);
    }

    // s0: all-m attn logits (one 2D launch) after all aggs
    for (int m = 0; m < MM; m++)
        cudaStreamWaitEvent(0, evAg[m], 0);
    dim3 gattn(gnb, MM);
    k_attnlogits<<<gattn, 128>>>(fc_W, fc_b, attn);

    // s0: combine
    k_combine<<<gab, 256>>>(out);
}